// round 13
// baseline (speedup 1.0000x reference)
#include <cuda_runtime.h>
#include <cuda_fp16.h>
#include <cstdint>
#include <math.h>

#define B_ 4
#define N_ 4096
#define D_ 128
#define HS 136                    // halves per smem row (272B stride)
#define TILE_H (128u * HS * 2u)   // 34816 B per 128-row fp16 tile
#define NT (N_ / 128)

// ---------------- scratch (device globals; no runtime allocation) ----------
__device__ __half g_q[B_ * N_ * D_];
__device__ __half g_k[B_ * N_ * D_];
__device__ __half g_v[B_ * N_ * D_];
__device__ float  g_att[B_ * N_ * D_];
__device__ __half g_h[B_ * N_ * D_];

// ======================= helpers ===========================================
__device__ __forceinline__ uint32_t smem_u32(const void* p) {
    uint32_t a;
    asm("{ .reg .u64 t; cvta.to.shared.u64 t, %1; cvt.u32.u64 %0, t; }"
        : "=r"(a) : "l"(p));
    return a;
}

__device__ __forceinline__ float ex2f(float x) {
    float r;
    asm("ex2.approx.ftz.f32 %0, %1;" : "=f"(r) : "f"(x));
    return r;
}

__device__ __forceinline__ uint32_t f2h2(float a, float b) {
    __half2 h = __floats2half2_rn(a, b);
    return *reinterpret_cast<uint32_t*>(&h);
}

__device__ __forceinline__ void sts64(uint32_t addr, uint32_t lo, uint32_t hi) {
    asm volatile("st.shared.v2.b32 [%0], {%1,%2};" :: "r"(addr), "r"(lo), "r"(hi) : "memory");
}
__device__ __forceinline__ void sts128u(uint32_t addr, uint4 v) {
    asm volatile("st.shared.v4.b32 [%0], {%1,%2,%3,%4};"
        :: "r"(addr), "r"(v.x), "r"(v.y), "r"(v.z), "r"(v.w) : "memory");
}

__device__ __forceinline__ void cp16(uint32_t dst, const void* src) {
    asm volatile("cp.async.cg.shared.global [%0], [%1], 16;"
        :: "r"(dst), "l"(src) : "memory");
}
#define CP_COMMIT() asm volatile("cp.async.commit_group;" ::: "memory")
#define CP_WAIT0()  asm volatile("cp.async.wait_group 0;" ::: "memory")

__device__ __forceinline__ void ldsm_x4(uint32_t& r0, uint32_t& r1, uint32_t& r2, uint32_t& r3,
                                        uint32_t addr) {
    asm volatile("ldmatrix.sync.aligned.m8n8.x4.shared.b16 {%0,%1,%2,%3}, [%4];"
        : "=r"(r0), "=r"(r1), "=r"(r2), "=r"(r3) : "r"(addr));
}
__device__ __forceinline__ void ldsm_x4_t(uint32_t& r0, uint32_t& r1, uint32_t& r2, uint32_t& r3,
                                          uint32_t addr) {
    asm volatile("ldmatrix.sync.aligned.m8n8.x4.trans.shared.b16 {%0,%1,%2,%3}, [%4];"
        : "=r"(r0), "=r"(r1), "=r"(r2), "=r"(r3) : "r"(addr));
}

// D(16x8,f32) += A(16x16,f16 row) * B(16x8,f16 col)
__device__ __forceinline__ void mma_f16(float* d,
                                        uint32_t a0, uint32_t a1, uint32_t a2, uint32_t a3,
                                        uint32_t b0, uint32_t b1) {
    asm volatile(
        "mma.sync.aligned.m16n8k16.row.col.f32.f16.f16.f32 "
        "{%0,%1,%2,%3}, {%4,%5,%6,%7}, {%8,%9}, {%0,%1,%2,%3};"
        : "+f"(d[0]), "+f"(d[1]), "+f"(d[2]), "+f"(d[3])
        : "r"(a0), "r"(a1), "r"(a2), "r"(a3), "r"(b0), "r"(b1));
}

// ---------------------------------------------------------------------------
// fp16 flash attention, FA2 structure (measured 167us in R12):
// 8 warps, each 16 q-rows x full 128 kv. P stays in registers.
// Fixed-shift softmax (C=3); eye handled in a UNIFORM branch (ct==blockIdx.x).
// One __syncthreads per kv iteration.
// Smem: Qh | K0 | V0 | K1 | V1 = 5 * 34816 B (cp.async double-buffered K/V)
// ---------------------------------------------------------------------------
__global__ __launch_bounds__(256, 1) void attn_f16(
    const __half* __restrict__ Q, const __half* __restrict__ K,
    const __half* __restrict__ V, const float* __restrict__ adj,
    const float* __restrict__ X, float* __restrict__ Out)
{
    extern __shared__ __align__(16) char smraw[];
    const uint32_t Qb = smem_u32(smraw);
    const uint32_t Kt[2] = { Qb + 1u * TILE_H, Qb + 3u * TILE_H };
    const uint32_t Vt[2] = { Qb + 2u * TILE_H, Qb + 4u * TILE_H };

    const int tid  = threadIdx.x;
    const int wid  = tid >> 5;      // 0..7 -> q rows [16*wid, 16*wid+16)
    const int lane = tid & 31;
    const int gq   = lane >> 2;
    const int tq   = lane & 3;
    const int lr   = lane & 7;
    const int g8   = lane >> 3;
    const int b    = blockIdx.y;
    const int q0   = blockIdx.x * 128;

    // ldmatrix per-lane address components (validated R6/R8/R9)
    const int arow = lr + ((g8 & 1) ? 8 : 0);   // A-type (Q)
    const int acol = (g8 & 2) ? 8 : 0;
    const int brow = lr + ((g8 & 2) ? 8 : 0);   // B-type (K)
    const int bcol = (g8 & 1) ? 8 : 0;
    const int vrow = lr + ((g8 & 1) ? 8 : 0);   // B-trans (V)
    const int vcol = (g8 & 2) ? 8 : 0;

    // ---- prologue: cp.async Q + K0 + V0 ----
    {
        const __half* Qg = Q + ((size_t)b * N_ + q0) * D_;
        const __half* Kg = K + ((size_t)b * N_) * D_;
        const __half* Vg = V + ((size_t)b * N_) * D_;
#pragma unroll
        for (int it = 0; it < 8; ++it) {
            int idx = tid + it * 256;          // 2048 16B-chunks per tile
            int r = idx >> 4, c = idx & 15;
            uint32_t off = (uint32_t)(r * HS + c * 8) * 2u;
            const size_t gsrc = (size_t)r * D_ + c * 8;
            cp16(Qb    + off, Qg + gsrc);
            cp16(Kt[0] + off, Kg + gsrc);
            cp16(Vt[0] + off, Vg + gsrc);
        }
    }
    CP_COMMIT();
    CP_WAIT0();
    __syncthreads();

    const float scaleL = 0.088388347648318447f * 1.4426950408889634f;  // scale*log2e
    const float LOG2E  = 1.4426950408889634f;
    const float C      = 3.0f;
    const float NCL    = -C * LOG2E;

    const int tr0 = q0 + wid * 16 + gq;   // global q row of c0/c1
    const int tr1 = tr0 + 8;              // global q row of c2/c3

    float lsum0 = 0.f, lsum1 = 0.f;
    float Oacc[16][4];
#pragma unroll
    for (int nt = 0; nt < 16; ++nt)
#pragma unroll
        for (int j = 0; j < 4; ++j) Oacc[nt][j] = 0.f;

    for (int ct = 0; ct < NT; ++ct) {
        const uint32_t Kb = Kt[ct & 1];
        const uint32_t Vb = Vt[ct & 1];

        // ---- prefetch next K/V into the other buffer (overlaps compute) ----
        if (ct + 1 < NT) {
            const __half* Kg = K + ((size_t)b * N_ + (ct + 1) * 128) * D_;
            const __half* Vg = V + ((size_t)b * N_ + (ct + 1) * 128) * D_;
            const uint32_t kd = Kt[(ct + 1) & 1];
            const uint32_t vd = Vt[(ct + 1) & 1];
#pragma unroll
            for (int it = 0; it < 8; ++it) {
                int idx = tid + it * 256;
                int r = idx >> 4, c = idx & 15;
                uint32_t off = (uint32_t)(r * HS + c * 8) * 2u;
                const size_t gsrc = (size_t)r * D_ + c * 8;
                cp16(kd + off, Kg + gsrc);
                cp16(vd + off, Vg + gsrc);
            }
            CP_COMMIT();
        }

        // ---- MMA1: S = Q @ K^T  (warp tile 16 q x 128 kv) ----
        float Sacc[16][4];
#pragma unroll
        for (int nt = 0; nt < 16; ++nt)
#pragma unroll
            for (int j = 0; j < 4; ++j) Sacc[nt][j] = 0.f;

#pragma unroll
        for (int ks = 0; ks < 8; ++ks) {
            uint32_t qa0, qa1, qa2, qa3;
            ldsm_x4(qa0, qa1, qa2, qa3,
                    Qb + (uint32_t)((wid * 16 + arow) * HS + ks * 16 + acol) * 2u);
#pragma unroll
            for (int np = 0; np < 8; ++np) {
                uint32_t r0, r1, r2, r3;
                ldsm_x4(r0, r1, r2, r3,
                        Kb + (uint32_t)((np * 16 + brow) * HS + ks * 16 + bcol) * 2u);
                mma_f16(Sacc[np * 2],     qa0, qa1, qa2, qa3, r0, r1);
                mma_f16(Sacc[np * 2 + 1], qa0, qa1, qa2, qa3, r2, r3);
            }
        }

        // ---- softmax (fixed shift), P packed to half2 in registers ----
        uint32_t ph[16][2];
        if (ct == blockIdx.x) {
            // diagonal tile: eye term present (uniform branch, 1/32 iters)
#pragma unroll
            for (int nt = 0; nt < 16; ++nt) {
                int cg = ct * 128 + nt * 8 + 2 * tq;
                float2 aj0 = *reinterpret_cast<const float2*>(adj + (size_t)tr0 * N_ + cg);
                float2 aj1 = *reinterpret_cast<const float2*>(adj + (size_t)tr1 * N_ + cg);
                float p0 = ex2f(fmaf(Sacc[nt][0], scaleL,
                                     (aj0.x + ((tr0 == cg)     ? 1.f : 0.f) - C) * LOG2E));
                float p1 = ex2f(fmaf(Sacc[nt][1], scaleL,
                                     (aj0.y + ((tr0 == cg + 1) ? 1.f : 0.f) - C) * LOG2E));
                float p2 = ex2f(fmaf(Sacc[nt][2], scaleL,
                                     (aj1.x + ((tr1 == cg)     ? 1.f : 0.f) - C) * LOG2E));
                float p3 = ex2f(fmaf(Sacc[nt][3], scaleL,
                                     (aj1.y + ((tr1 == cg + 1) ? 1.f : 0.f) - C) * LOG2E));
                lsum0 += p0 + p1;
                lsum1 += p2 + p3;
                ph[nt][0] = f2h2(p0, p1);
                ph[nt][1] = f2h2(p2, p3);
            }
        } else {
            // off-diagonal: p = ex2(adj*log2e + (S*scaleL - C*log2e))
#pragma unroll
            for (int nt = 0; nt < 16; ++nt) {
                int cg = ct * 128 + nt * 8 + 2 * tq;
                float2 aj0 = *reinterpret_cast<const float2*>(adj + (size_t)tr0 * N_ + cg);
                float2 aj1 = *reinterpret_cast<const float2*>(adj + (size_t)tr1 * N_ + cg);
                float p0 = ex2f(fmaf(aj0.x, LOG2E, fmaf(Sacc[nt][0], scaleL, NCL)));
                float p1 = ex2f(fmaf(aj0.y, LOG2E, fmaf(Sacc[nt][1], scaleL, NCL)));
                float p2 = ex2f(fmaf(aj1.x, LOG2E, fmaf(Sacc[nt][2], scaleL, NCL)));
                float p3 = ex2f(fmaf(aj1.y, LOG2E, fmaf(Sacc[nt][3], scaleL, NCL)));
                lsum0 += p0 + p1;
                lsum1 += p2 + p3;
                ph[nt][0] = f2h2(p0, p1);
                ph[nt][1] = f2h2(p2, p3);
            }
        }

        // ---- MMA2: O += P(regs) @ V  (k = 128 kv, n = 128 d) ----
#pragma unroll
        for (int kk = 0; kk < 8; ++kk) {
            uint32_t a0 = ph[2 * kk][0];
            uint32_t a1 = ph[2 * kk][1];
            uint32_t a2 = ph[2 * kk + 1][0];
            uint32_t a3 = ph[2 * kk + 1][1];
#pragma unroll
            for (int np = 0; np < 8; ++np) {
                uint32_t r0, r1, r2, r3;
                ldsm_x4_t(r0, r1, r2, r3,
                          Vb + (uint32_t)((kk * 16 + vrow) * HS + np * 16 + vcol) * 2u);
                mma_f16(Oacc[np * 2],     a0, a1, a2, a3, r0, r1);
                mma_f16(Oacc[np * 2 + 1], a0, a1, a2, a3, r2, r3);
            }
        }

        CP_WAIT0();        // next K/V landed (had all of compute to arrive)
        __syncthreads();   // all warps done with this iter's buffers
    }

    // ---- epilogue: intra-warp l reduction, out = relu(O/l) + x ----
    lsum0 += __shfl_xor_sync(0xffffffffu, lsum0, 1);
    lsum0 += __shfl_xor_sync(0xffffffffu, lsum0, 2);
    lsum1 += __shfl_xor_sync(0xffffffffu, lsum1, 1);
    lsum1 += __shfl_xor_sync(0xffffffffu, lsum1, 2);
    const float linv0 = 1.f / lsum0;
    const float linv1 = 1.f / lsum1;

#pragma unroll
    for (int nt = 0; nt < 16; ++nt) {
        int col = nt * 8 + 2 * tq;
        size_t base0 = ((size_t)b * N_ + tr0) * D_ + col;
        size_t base1 = ((size_t)b * N_ + tr1) * D_ + col;
        float2 x0 = *reinterpret_cast<const float2*>(X + base0);
        float2 x1 = *reinterpret_cast<const float2*>(X + base1);
        float2 o0, o1;
        o0.x = fmaxf(Oacc[nt][0] * linv0, 0.f) + x0.x;
        o0.y = fmaxf(Oacc[nt][1] * linv0, 0.f) + x0.y;
        o1.x = fmaxf(Oacc[nt][2] * linv1, 0.f) + x1.x;
        o1.y = fmaxf(Oacc[nt][3] * linv1, 0.f) + x1.y;
        *reinterpret_cast<float2*>(Out + base0) = o0;
        *reinterpret_cast<float2*>(Out + base1) = o1;
    }
}

// ---------------------------------------------------------------------------
// Fused QKV GEMM: stage X once + 3 W tiles; three mainloops; fp16 outputs.
// Smem: Xb | Wq | Wk | Wv = 4 * 34816 = 139264 B.
// ---------------------------------------------------------------------------
__global__ __launch_bounds__(256) void gemm_qkv(
    const float* __restrict__ X,
    const float* __restrict__ Wq, const float* __restrict__ bq,
    const float* __restrict__ Wk, const float* __restrict__ bk,
    const float* __restrict__ Wv, const float* __restrict__ bv,
    __half* __restrict__ Qo, __half* __restrict__ Ko, __half* __restrict__ Vo)
{
    extern __shared__ __align__(16) char smraw[];
    const uint32_t Xb = smem_u32(smraw);

    const int tid  = threadIdx.x;
    const int wid  = tid >> 5;
    const int lane = tid & 31;
    const int w_m  = wid & 3;
    const int w_n  = wid >> 2;
    const int gq   = lane >> 2;
    const int tq   = lane & 3;
    const int lr   = lane & 7;
    const int g8   = lane >> 3;
    const int row0 = blockIdx.x * 128;

    const int arow = lr + ((g8 & 1) ? 8 : 0);
    const int acol = (g8 & 2) ? 8 : 0;
    const int brow = lr + ((g8 & 2) ? 8 : 0);
    const int bcol = (g8 & 1) ? 8 : 0;

    // ---- stage X + Wq + Wk + Wv (fp32 -> fp16) ----
    {
        const float4* Xg  = reinterpret_cast<const float4*>(X + (size_t)row0 * D_);
        const float4* Wg0 = reinterpret_cast<const float4*>(Wq);
        const float4* Wg1 = reinterpret_cast<const float4*>(Wk);
        const float4* Wg2 = reinterpret_cast<const float4*>(Wv);
#pragma unroll
        for (int it = 0; it < 16; ++it) {
            int idx = tid + it * 256;
            int r = idx >> 5, c4 = idx & 31;
            uint32_t off = (uint32_t)(r * HS + c4 * 4) * 2u;
            float4 x4 = Xg[idx];
            sts64(Xb + off, f2h2(x4.x, x4.y), f2h2(x4.z, x4.w));
            float4 w0 = Wg0[idx];
            sts64(Xb + 1u * TILE_H + off, f2h2(w0.x, w0.y), f2h2(w0.z, w0.w));
            float4 w1 = Wg1[idx];
            sts64(Xb + 2u * TILE_H + off, f2h2(w1.x, w1.y), f2h2(w1.z, w1.w));
            float4 w2 = Wg2[idx];
            sts64(Xb + 3u * TILE_H + off, f2h2(w2.x, w2.y), f2h2(w2.z, w2.w));
        }
    }
    __syncthreads();

    const float* bs[3] = { bq, bk, bv };
    __half* Os[3] = { Qo, Ko, Vo };

    for (int w = 0; w < 3; ++w) {
        const uint32_t Wb = Xb + (uint32_t)(w + 1) * TILE_H;
        float acc[2][8][4];
#pragma unroll
        for (int mi = 0; mi < 2; ++mi)
#pragma unroll
            for (int nt = 0; nt < 8; ++nt)
#pragma unroll
                for (int j = 0; j < 4; ++j) acc[mi][nt][j] = 0.f;

#pragma unroll
        for (int ks = 0; ks < 8; ++ks) {
            uint32_t xa[2][4];
#pragma unroll
            for (int mi = 0; mi < 2; ++mi)
                ldsm_x4(xa[mi][0], xa[mi][1], xa[mi][2], xa[mi][3],
                        Xb + (uint32_t)((w_m * 32 + mi * 16 + arow) * HS + ks * 16 + acol) * 2u);
#pragma unroll
            for (int np = 0; np < 4; ++np) {
                uint32_t r0, r1, r2, r3;
                ldsm_x4(r0, r1, r2, r3,
                        Wb + (uint32_t)((w_n * 64 + np * 16 + brow) * HS + ks * 16 + bcol) * 2u);
#pragma unroll
                for (int mi = 0; mi < 2; ++mi) {
                    mma_f16(acc[mi][np * 2],     xa[mi][0], xa[mi][1], xa[mi][2], xa[mi][3], r0, r1);
                    mma_f16(acc[mi][np * 2 + 1], xa[mi][0], xa[mi][1], xa[mi][2], xa[mi][3], r2, r3);
                }
            }
        }

        const float* bias = bs[w];
        __half* Yv = Os[w];
#pragma unroll
        for (int mi = 0; mi < 2; ++mi)
#pragma unroll
            for (int hi = 0; hi < 2; ++hi) {
                const int row = row0 + w_m * 32 + mi * 16 + hi * 8 + gq;
#pragma unroll
                for (int nt = 0; nt < 8; ++nt) {
                    int col = w_n * 64 + nt * 8 + 2 * tq;
                    float2 bb = *reinterpret_cast<const float2*>(bias + col);
                    float v0 = acc[mi][nt][hi * 2]     + bb.x;
                    float v1 = acc[mi][nt][hi * 2 + 1] + bb.y;
                    *reinterpret_cast<uint32_t*>(Yv + (size_t)row * D_ + col) = f2h2(v0, v1);
                }
            }
    }
}

// ---------------------------------------------------------------------------
// fp16 tensor GEMM: Y[M,128] = act(X[M,128] @ W^T[128,128] + b) (+ resid)
// Compile-time specialized on input/output dtype (validated R11/R12).
// ---------------------------------------------------------------------------
template <int IN_HALF, int OUT_HALF>
__global__ __launch_bounds__(256) void gemm_f16(
    const void* __restrict__ Xv, const float* __restrict__ W,
    const float* __restrict__ bias, const float* __restrict__ resid,
    void* __restrict__ Yv, int do_relu)
{
    extern __shared__ __align__(16) char smraw[];
    const uint32_t Xb = smem_u32(smraw);
    const uint32_t Wb = Xb + TILE_H;

    const int tid  = threadIdx.x;
    const int wid  = tid >> 5;
    const int lane = tid & 31;
    const int w_m  = wid & 3;
    const int w_n  = wid >> 2;
    const int gq   = lane >> 2;
    const int tq   = lane & 3;
    const int lr   = lane & 7;
    const int g8   = lane >> 3;
    const int row0 = blockIdx.x * 128;

    const int arow = lr + ((g8 & 1) ? 8 : 0);
    const int acol = (g8 & 2) ? 8 : 0;
    const int brow = lr + ((g8 & 2) ? 8 : 0);
    const int bcol = (g8 & 1) ? 8 : 0;

    // ---- stage W (fp32 -> fp16) ----
    {
        const float4* Wg = reinterpret_cast<const float4*>(W);
#pragma unroll
        for (int it = 0; it < 16; ++it) {
            int idx = tid + it * 256;
            int r = idx >> 5, c4 = idx & 31;
            float4 w4 = Wg[idx];
            sts64(Wb + (uint32_t)(r * HS + c4 * 4) * 2u, f2h2(w4.x, w4.y), f2h2(w4.z, w4.w));
        }
    }
    // ---- stage X ----
    if (IN_HALF) {
        const uint4* Xg = reinterpret_cast<const uint4*>(
            reinterpret_cast<const __half*>(Xv) + (size_t)row0 * D_);
#pragma unroll
        for (int it = 0; it < 8; ++it) {
            int idx = tid + it * 256;          // 2048 16B chunks = 128 rows x 16
            int r = idx >> 4, c = idx & 15;
            sts128u(Xb + (uint32_t)(r * HS + c * 8) * 2u, Xg[r * 16 + c]);
        }
    } else {
        const float4* Xg = reinterpret_cast<const float4*>(
            reinterpret_cast<const float*>(Xv) + (size_t)row0 * D_);
#pragma unroll
        for (int it = 0; it < 16; ++it) {
            int idx = tid + it * 256;
            int r = idx >> 5, c4 = idx & 31;
            float4 x4 = Xg[idx];
            sts64(Xb + (uint32_t)(r * HS + c4 * 4) * 2u, f2h2(x4.x, x4.y), f2h2(x4.z, x4.w));
        }
    }
    __syncthreads();

    float acc[2][8][4];
#pragma unroll
    for (int mi = 0; mi < 2; ++mi)
#pragma unroll
        for (int nt = 0; nt < 8; ++nt)
#pragma unroll
            for (int j = 0; j < 4; ++j) acc[mi][nt][j] = 0.f;

#pragma unroll
    for (int ks = 0; ks < 8; ++ks) {
        uint32_t xa[2][4];
#pragma unroll
        for (int mi = 0; mi < 2; ++mi)
            ldsm_x4(xa[mi][0], xa[mi][1], xa[mi][2], xa[mi][3],
                    Xb + (uint32_t)((w_m * 32 + mi * 16 + arow) * HS + ks * 16 + acol) * 2u);
#pragma unroll
        for (int np = 0; np < 4; ++np) {
            uint32_t r0, r1, r2, r3;
            ldsm_x4(r0, r1, r2, r3,
                    Wb + (uint32_t)((w_n * 64 + np * 16 + brow) * HS + ks * 16 + bcol) * 2u);
#pragma unroll
            for (int mi = 0; mi < 2; ++mi) {
                mma_f16(acc[mi][np * 2],     xa[mi][0], xa[mi][1], xa[mi][2], xa[mi][3], r0, r1);
                mma_f16(acc[mi][np * 2 + 1], xa[mi][0], xa[mi][1], xa[mi][2], xa[mi][3], r2, r3);
            }
        }
    }

#pragma unroll
    for (int mi = 0; mi < 2; ++mi)
#pragma unroll
        for (int hi = 0; hi < 2; ++hi) {
            const int row = row0 + w_m * 32 + mi * 16 + hi * 8 + gq;
#pragma unroll
            for (int nt = 0; nt < 8; ++nt) {
                int col = w_n * 64 + nt * 8 + 2 * tq;
                float2 bb = *reinterpret_cast<const float2*>(bias + col);
                float v0 = acc[mi][nt][hi * 2]     + bb.x;
                float v1 = acc[mi][nt][hi * 2 + 1] + bb.y;
                if (do_relu) { v0 = fmaxf(v0, 0.f); v1 = fmaxf(v1, 0.f); }
                size_t base = (size_t)row * D_ + col;
                if (resid) {
                    float2 r2 = *reinterpret_cast<const float2*>(resid + base);
                    v0 += r2.x; v1 += r2.y;
                }
                if (OUT_HALF) {
                    *reinterpret_cast<uint32_t*>(reinterpret_cast<__half*>(Yv) + base) =
                        f2h2(v0, v1);
                } else {
                    *reinterpret_cast<float2*>(reinterpret_cast<float*>(Yv) + base) =
                        make_float2(v0, v1);
                }
            }
        }
}

// ---------------------------------------------------------------------------
extern "C" void kernel_launch(void* const* d_in, const int* in_sizes, int n_in,
                              void* d_out, int out_size)
{
    const float* x   = (const float*)d_in[0];
    const float* adj = (const float*)d_in[1];
    const float* Wq  = (const float*)d_in[2];
    const float* bq  = (const float*)d_in[3];
    const float* Wk  = (const float*)d_in[4];
    const float* bk  = (const float*)d_in[5];
    const float* Wv  = (const float*)d_in[6];
    const float* bv  = (const float*)d_in[7];
    const float* W1  = (const float*)d_in[8];
    const float* b1  = (const float*)d_in[9];
    const float* W2  = (const float*)d_in[10];
    const float* b2  = (const float*)d_in[11];
    float* out = (float*)d_out;

    __half *q, *k, *v, *hbuf;
    float *att;
    cudaGetSymbolAddress((void**)&q,    g_q);
    cudaGetSymbolAddress((void**)&k,    g_k);
    cudaGetSymbolAddress((void**)&v,    g_v);
    cudaGetSymbolAddress((void**)&att,  g_att);
    cudaGetSymbolAddress((void**)&hbuf, g_h);

    const int M = B_ * N_;
    const size_t gemm_smem = 2u * TILE_H;   // 69632 B
    const size_t qkv_smem  = 4u * TILE_H;   // 139264 B
    const size_t attn_smem = 5u * TILE_H;   // 174080 B
    cudaFuncSetAttribute(gemm_qkv,      cudaFuncAttributeMaxDynamicSharedMemorySize, (int)qkv_smem);
    cudaFuncSetAttribute(gemm_f16<0,1>, cudaFuncAttributeMaxDynamicSharedMemorySize, (int)gemm_smem);
    cudaFuncSetAttribute(gemm_f16<1,0>, cudaFuncAttributeMaxDynamicSharedMemorySize, (int)gemm_smem);
    cudaFuncSetAttribute(attn_f16,      cudaFuncAttributeMaxDynamicSharedMemorySize, (int)attn_smem);

    gemm_qkv<<<M / 128, 256, qkv_smem>>>(x, Wq, bq, Wk, bk, Wv, bv, q, k, v);

    dim3 ag(N_ / 128, B_);
    attn_f16<<<ag, 256, attn_smem>>>(q, k, v, adj, x, att);

    // FFN: h(fp16) = relu(att @ W1^T + b1); out = relu(h @ W2^T + b2) + att
    gemm_f16<0,1><<<M / 128, 256, gemm_smem>>>(att, W1, b1, nullptr, hbuf, 1);
    gemm_f16<1,0><<<M / 128, 256, gemm_smem>>>(hbuf, W2, b2, att, out, 1);
}

// round 14
// speedup vs baseline: 1.0094x; 1.0094x over previous
#include <cuda_runtime.h>
#include <cuda_fp16.h>
#include <cstdint>
#include <math.h>

#define B_ 4
#define N_ 4096
#define D_ 128
#define HS 136                    // halves per smem row (272B stride)
#define TILE_H (128u * HS * 2u)   // 34816 B per 128-row fp16 tile
#define QTILE_H (64u * HS * 2u)   // 17408 B per 64-row fp16 tile
#define NT (N_ / 128)

// ---------------- scratch (device globals; no runtime allocation) ----------
__device__ __half g_q[B_ * N_ * D_];
__device__ __half g_k[B_ * N_ * D_];
__device__ __half g_v[B_ * N_ * D_];
__device__ float  g_att[B_ * N_ * D_];
__device__ __half g_h[B_ * N_ * D_];

// ======================= helpers ===========================================
__device__ __forceinline__ uint32_t smem_u32(const void* p) {
    uint32_t a;
    asm("{ .reg .u64 t; cvta.to.shared.u64 t, %1; cvt.u32.u64 %0, t; }"
        : "=r"(a) : "l"(p));
    return a;
}

__device__ __forceinline__ float ex2f(float x) {
    float r;
    asm("ex2.approx.ftz.f32 %0, %1;" : "=f"(r) : "f"(x));
    return r;
}

__device__ __forceinline__ uint32_t f2h2(float a, float b) {
    __half2 h = __floats2half2_rn(a, b);
    return *reinterpret_cast<uint32_t*>(&h);
}

__device__ __forceinline__ void sts64(uint32_t addr, uint32_t lo, uint32_t hi) {
    asm volatile("st.shared.v2.b32 [%0], {%1,%2};" :: "r"(addr), "r"(lo), "r"(hi) : "memory");
}
__device__ __forceinline__ void sts128u(uint32_t addr, uint4 v) {
    asm volatile("st.shared.v4.b32 [%0], {%1,%2,%3,%4};"
        :: "r"(addr), "r"(v.x), "r"(v.y), "r"(v.z), "r"(v.w) : "memory");
}

__device__ __forceinline__ void cp16(uint32_t dst, const void* src) {
    asm volatile("cp.async.cg.shared.global [%0], [%1], 16;"
        :: "r"(dst), "l"(src) : "memory");
}
#define CP_COMMIT() asm volatile("cp.async.commit_group;" ::: "memory")
#define CP_WAIT0()  asm volatile("cp.async.wait_group 0;" ::: "memory")

__device__ __forceinline__ void ldsm_x4(uint32_t& r0, uint32_t& r1, uint32_t& r2, uint32_t& r3,
                                        uint32_t addr) {
    asm volatile("ldmatrix.sync.aligned.m8n8.x4.shared.b16 {%0,%1,%2,%3}, [%4];"
        : "=r"(r0), "=r"(r1), "=r"(r2), "=r"(r3) : "r"(addr));
}
__device__ __forceinline__ void ldsm_x4_t(uint32_t& r0, uint32_t& r1, uint32_t& r2, uint32_t& r3,
                                          uint32_t addr) {
    asm volatile("ldmatrix.sync.aligned.m8n8.x4.trans.shared.b16 {%0,%1,%2,%3}, [%4];"
        : "=r"(r0), "=r"(r1), "=r"(r2), "=r"(r3) : "r"(addr));
}

// D(16x8,f32) += A(16x16,f16 row) * B(16x8,f16 col)
__device__ __forceinline__ void mma_f16(float* d,
                                        uint32_t a0, uint32_t a1, uint32_t a2, uint32_t a3,
                                        uint32_t b0, uint32_t b1) {
    asm volatile(
        "mma.sync.aligned.m16n8k16.row.col.f32.f16.f16.f32 "
        "{%0,%1,%2,%3}, {%4,%5,%6,%7}, {%8,%9}, {%0,%1,%2,%3};"
        : "+f"(d[0]), "+f"(d[1]), "+f"(d[2]), "+f"(d[3])
        : "r"(a0), "r"(a1), "r"(a2), "r"(a3), "r"(b0), "r"(b1));
}

// ---------------------------------------------------------------------------
// fp16 flash attention, FA2 register-P, q-tile 64 / 4 warps / 2 CTAs per SM:
// each warp: 16 q-rows x full 128 kv. Single-buffered K/V (co-resident CTA
// hides the load wait). Fixed-shift softmax (C=3). Grid (N/64, B).
// Smem: Qh(64r) | K | V = 17408 + 2*34816 = 87040 B -> 2 CTAs/SM.
// ---------------------------------------------------------------------------
__global__ __launch_bounds__(128, 2) void attn_f16(
    const __half* __restrict__ Q, const __half* __restrict__ K,
    const __half* __restrict__ V, const float* __restrict__ adj,
    const float* __restrict__ X, float* __restrict__ Out)
{
    extern __shared__ __align__(16) char smraw[];
    const uint32_t Qb = smem_u32(smraw);
    const uint32_t Kb = Qb + QTILE_H;
    const uint32_t Vb = Kb + TILE_H;

    const int tid  = threadIdx.x;
    const int wid  = tid >> 5;      // 0..3 -> q rows [16*wid, 16*wid+16)
    const int lane = tid & 31;
    const int gq   = lane >> 2;
    const int tq   = lane & 3;
    const int lr   = lane & 7;
    const int g8   = lane >> 3;
    const int b    = blockIdx.y;
    const int q0   = blockIdx.x * 64;

    // ldmatrix per-lane address components (validated R6/R8/R9)
    const int arow = lr + ((g8 & 1) ? 8 : 0);   // A-type (Q)
    const int acol = (g8 & 2) ? 8 : 0;
    const int brow = lr + ((g8 & 2) ? 8 : 0);   // B-type (K)
    const int bcol = (g8 & 1) ? 8 : 0;
    const int vrow = lr + ((g8 & 1) ? 8 : 0);   // B-trans (V)
    const int vcol = (g8 & 2) ? 8 : 0;

    // ---- prologue: cp.async Q (64 rows) ----
    {
        const __half* Qg = Q + ((size_t)b * N_ + q0) * D_;
#pragma unroll
        for (int it = 0; it < 8; ++it) {
            int idx = tid + it * 128;          // 1024 16B-chunks
            int r = idx >> 4, c = idx & 15;
            cp16(Qb + (uint32_t)(r * HS + c * 8) * 2u, Qg + (size_t)r * D_ + c * 8);
        }
    }
    CP_COMMIT();

    const float scaleL = 0.088388347648318447f * 1.4426950408889634f;  // scale*log2e
    const float LOG2E  = 1.4426950408889634f;
    const float C      = 3.0f;

    const int tr0 = q0 + wid * 16 + gq;   // global q row of c0/c1
    const int tr1 = tr0 + 8;              // global q row of c2/c3

    float lsum0 = 0.f, lsum1 = 0.f;
    float Oacc[16][4];
#pragma unroll
    for (int nt = 0; nt < 16; ++nt)
#pragma unroll
        for (int j = 0; j < 4; ++j) Oacc[nt][j] = 0.f;

    for (int ct = 0; ct < NT; ++ct) {
        // ---- load this iter's K/V (single buffer; co-CTA hides the wait) ----
        {
            const __half* Kg = K + ((size_t)b * N_ + ct * 128) * D_;
            const __half* Vg = V + ((size_t)b * N_ + ct * 128) * D_;
#pragma unroll
            for (int it = 0; it < 16; ++it) {
                int idx = tid + it * 128;      // 2048 16B-chunks per tile
                int r = idx >> 4, c = idx & 15;
                uint32_t off = (uint32_t)(r * HS + c * 8) * 2u;
                const size_t gsrc = (size_t)r * D_ + c * 8;
                cp16(Kb + off, Kg + gsrc);
                cp16(Vb + off, Vg + gsrc);
            }
        }
        CP_COMMIT();
        CP_WAIT0();
        __syncthreads();

        // ---- MMA1: S = Q @ K^T  (warp tile 16 q x 128 kv) ----
        float Sacc[16][4];
#pragma unroll
        for (int nt = 0; nt < 16; ++nt)
#pragma unroll
            for (int j = 0; j < 4; ++j) Sacc[nt][j] = 0.f;

#pragma unroll
        for (int ks = 0; ks < 8; ++ks) {
            uint32_t qa0, qa1, qa2, qa3;
            ldsm_x4(qa0, qa1, qa2, qa3,
                    Qb + (uint32_t)((wid * 16 + arow) * HS + ks * 16 + acol) * 2u);
#pragma unroll
            for (int np = 0; np < 8; ++np) {
                uint32_t r0, r1, r2, r3;
                ldsm_x4(r0, r1, r2, r3,
                        Kb + (uint32_t)((np * 16 + brow) * HS + ks * 16 + bcol) * 2u);
                mma_f16(Sacc[np * 2],     qa0, qa1, qa2, qa3, r0, r1);
                mma_f16(Sacc[np * 2 + 1], qa0, qa1, qa2, qa3, r2, r3);
            }
        }

        // ---- softmax (fixed shift), P packed to half2 in registers ----
        uint32_t ph[16][2];
#pragma unroll
        for (int nt = 0; nt < 16; ++nt) {
            int cg = ct * 128 + nt * 8 + 2 * tq;
            float2 aj0 = *reinterpret_cast<const float2*>(adj + (size_t)tr0 * N_ + cg);
            float2 aj1 = *reinterpret_cast<const float2*>(adj + (size_t)tr1 * N_ + cg);
            float p0 = ex2f(fmaf(Sacc[nt][0], scaleL,
                                 (aj0.x + ((tr0 == cg)     ? 1.f : 0.f) - C) * LOG2E));
            float p1 = ex2f(fmaf(Sacc[nt][1], scaleL,
                                 (aj0.y + ((tr0 == cg + 1) ? 1.f : 0.f) - C) * LOG2E));
            float p2 = ex2f(fmaf(Sacc[nt][2], scaleL,
                                 (aj1.x + ((tr1 == cg)     ? 1.f : 0.f) - C) * LOG2E));
            float p3 = ex2f(fmaf(Sacc[nt][3], scaleL,
                                 (aj1.y + ((tr1 == cg + 1) ? 1.f : 0.f) - C) * LOG2E));
            lsum0 += p0 + p1;
            lsum1 += p2 + p3;
            ph[nt][0] = f2h2(p0, p1);   // rows gq   : MMA2 A-frag a0/a2
            ph[nt][1] = f2h2(p2, p3);   // rows gq+8 : MMA2 A-frag a1/a3
        }

        // ---- MMA2: O += P(regs) @ V  (k = 128 kv, n = 128 d) ----
#pragma unroll
        for (int kk = 0; kk < 8; ++kk) {
            uint32_t a0 = ph[2 * kk][0];
            uint32_t a1 = ph[2 * kk][1];
            uint32_t a2 = ph[2 * kk + 1][0];
            uint32_t a3 = ph[2 * kk + 1][1];
#pragma unroll
            for (int np = 0; np < 8; ++np) {
                uint32_t r0, r1, r2, r3;
                ldsm_x4_t(r0, r1, r2, r3,
                          Vb + (uint32_t)((kk * 16 + vrow) * HS + np * 16 + vcol) * 2u);
                mma_f16(Oacc[np * 2],     a0, a1, a2, a3, r0, r1);
                mma_f16(Oacc[np * 2 + 1], a0, a1, a2, a3, r2, r3);
            }
        }

        __syncthreads();   // all warps done with Kb/Vb before next overwrite
    }

    // ---- epilogue: intra-warp l reduction, out = relu(O/l) + x ----
    lsum0 += __shfl_xor_sync(0xffffffffu, lsum0, 1);
    lsum0 += __shfl_xor_sync(0xffffffffu, lsum0, 2);
    lsum1 += __shfl_xor_sync(0xffffffffu, lsum1, 1);
    lsum1 += __shfl_xor_sync(0xffffffffu, lsum1, 2);
    const float linv0 = 1.f / lsum0;
    const float linv1 = 1.f / lsum1;

#pragma unroll
    for (int nt = 0; nt < 16; ++nt) {
        int col = nt * 8 + 2 * tq;
        size_t base0 = ((size_t)b * N_ + tr0) * D_ + col;
        size_t base1 = ((size_t)b * N_ + tr1) * D_ + col;
        float2 x0 = *reinterpret_cast<const float2*>(X + base0);
        float2 x1 = *reinterpret_cast<const float2*>(X + base1);
        float2 o0, o1;
        o0.x = fmaxf(Oacc[nt][0] * linv0, 0.f) + x0.x;
        o0.y = fmaxf(Oacc[nt][1] * linv0, 0.f) + x0.y;
        o1.x = fmaxf(Oacc[nt][2] * linv1, 0.f) + x1.x;
        o1.y = fmaxf(Oacc[nt][3] * linv1, 0.f) + x1.y;
        *reinterpret_cast<float2*>(Out + base0) = o0;
        *reinterpret_cast<float2*>(Out + base1) = o1;
    }
}

// ---------------------------------------------------------------------------
// fp16 tensor GEMM: Y[M,128] = act(X[M,128] @ W^T[128,128] + b) (+ resid)
// Compile-time specialized on input/output dtype (validated R11/R12).
// 256 thr = 8 warps, 4x2 grid, CTA tile 128x128, K=128.
// ---------------------------------------------------------------------------
template <int IN_HALF, int OUT_HALF>
__global__ __launch_bounds__(256) void gemm_f16(
    const void* __restrict__ Xv, const float* __restrict__ W,
    const float* __restrict__ bias, const float* __restrict__ resid,
    void* __restrict__ Yv, int do_relu)
{
    extern __shared__ __align__(16) char smraw[];
    const uint32_t Xb = smem_u32(smraw);
    const uint32_t Wb = Xb + TILE_H;

    const int tid  = threadIdx.x;
    const int wid  = tid >> 5;
    const int lane = tid & 31;
    const int w_m  = wid & 3;
    const int w_n  = wid >> 2;
    const int gq   = lane >> 2;
    const int tq   = lane & 3;
    const int lr   = lane & 7;
    const int g8   = lane >> 3;
    const int row0 = blockIdx.x * 128;

    const int arow = lr + ((g8 & 1) ? 8 : 0);
    const int acol = (g8 & 2) ? 8 : 0;
    const int brow = lr + ((g8 & 2) ? 8 : 0);
    const int bcol = (g8 & 1) ? 8 : 0;

    // ---- stage W (fp32 -> fp16) ----
    {
        const float4* Wg = reinterpret_cast<const float4*>(W);
#pragma unroll
        for (int it = 0; it < 16; ++it) {
            int idx = tid + it * 256;
            int r = idx >> 5, c4 = idx & 31;
            float4 w4 = Wg[idx];
            sts64(Wb + (uint32_t)(r * HS + c4 * 4) * 2u, f2h2(w4.x, w4.y), f2h2(w4.z, w4.w));
        }
    }
    // ---- stage X ----
    if (IN_HALF) {
        const uint4* Xg = reinterpret_cast<const uint4*>(
            reinterpret_cast<const __half*>(Xv) + (size_t)row0 * D_);
#pragma unroll
        for (int it = 0; it < 8; ++it) {
            int idx = tid + it * 256;          // 2048 16B chunks = 128 rows x 16
            int r = idx >> 4, c = idx & 15;
            sts128u(Xb + (uint32_t)(r * HS + c * 8) * 2u, Xg[r * 16 + c]);
        }
    } else {
        const float4* Xg = reinterpret_cast<const float4*>(
            reinterpret_cast<const float*>(Xv) + (size_t)row0 * D_);
#pragma unroll
        for (int it = 0; it < 16; ++it) {
            int idx = tid + it * 256;
            int r = idx >> 5, c4 = idx & 31;
            float4 x4 = Xg[idx];
            sts64(Xb + (uint32_t)(r * HS + c4 * 4) * 2u, f2h2(x4.x, x4.y), f2h2(x4.z, x4.w));
        }
    }
    __syncthreads();

    float acc[2][8][4];
#pragma unroll
    for (int mi = 0; mi < 2; ++mi)
#pragma unroll
        for (int nt = 0; nt < 8; ++nt)
#pragma unroll
            for (int j = 0; j < 4; ++j) acc[mi][nt][j] = 0.f;

#pragma unroll
    for (int ks = 0; ks < 8; ++ks) {
        uint32_t xa[2][4];
#pragma unroll
        for (int mi = 0; mi < 2; ++mi)
            ldsm_x4(xa[mi][0], xa[mi][1], xa[mi][2], xa[mi][3],
                    Xb + (uint32_t)((w_m * 32 + mi * 16 + arow) * HS + ks * 16 + acol) * 2u);
#pragma unroll
        for (int np = 0; np < 4; ++np) {
            uint32_t r0, r1, r2, r3;
            ldsm_x4(r0, r1, r2, r3,
                    Wb + (uint32_t)((w_n * 64 + np * 16 + brow) * HS + ks * 16 + bcol) * 2u);
#pragma unroll
            for (int mi = 0; mi < 2; ++mi) {
                mma_f16(acc[mi][np * 2],     xa[mi][0], xa[mi][1], xa[mi][2], xa[mi][3], r0, r1);
                mma_f16(acc[mi][np * 2 + 1], xa[mi][0], xa[mi][1], xa[mi][2], xa[mi][3], r2, r3);
            }
        }
    }

#pragma unroll
    for (int mi = 0; mi < 2; ++mi)
#pragma unroll
        for (int hi = 0; hi < 2; ++hi) {
            const int row = row0 + w_m * 32 + mi * 16 + hi * 8 + gq;
#pragma unroll
            for (int nt = 0; nt < 8; ++nt) {
                int col = w_n * 64 + nt * 8 + 2 * tq;
                float2 bb = *reinterpret_cast<const float2*>(bias + col);
                float v0 = acc[mi][nt][hi * 2]     + bb.x;
                float v1 = acc[mi][nt][hi * 2 + 1] + bb.y;
                if (do_relu) { v0 = fmaxf(v0, 0.f); v1 = fmaxf(v1, 0.f); }
                size_t base = (size_t)row * D_ + col;
                if (resid) {
                    float2 r2 = *reinterpret_cast<const float2*>(resid + base);
                    v0 += r2.x; v1 += r2.y;
                }
                if (OUT_HALF) {
                    *reinterpret_cast<uint32_t*>(reinterpret_cast<__half*>(Yv) + base) =
                        f2h2(v0, v1);
                } else {
                    *reinterpret_cast<float2*>(reinterpret_cast<float*>(Yv) + base) =
                        make_float2(v0, v1);
                }
            }
        }
}

// ---------------------------------------------------------------------------
extern "C" void kernel_launch(void* const* d_in, const int* in_sizes, int n_in,
                              void* d_out, int out_size)
{
    const float* x   = (const float*)d_in[0];
    const float* adj = (const float*)d_in[1];
    const float* Wq  = (const float*)d_in[2];
    const float* bq  = (const float*)d_in[3];
    const float* Wk  = (const float*)d_in[4];
    const float* bk  = (const float*)d_in[5];
    const float* Wv  = (const float*)d_in[6];
    const float* bv  = (const float*)d_in[7];
    const float* W1  = (const float*)d_in[8];
    const float* b1  = (const float*)d_in[9];
    const float* W2  = (const float*)d_in[10];
    const float* b2  = (const float*)d_in[11];
    float* out = (float*)d_out;

    __half *q, *k, *v, *hbuf;
    float *att;
    cudaGetSymbolAddress((void**)&q,    g_q);
    cudaGetSymbolAddress((void**)&k,    g_k);
    cudaGetSymbolAddress((void**)&v,    g_v);
    cudaGetSymbolAddress((void**)&att,  g_att);
    cudaGetSymbolAddress((void**)&hbuf, g_h);

    const int M = B_ * N_;
    const size_t gemm_smem = 2u * TILE_H;              // 69632 B
    const size_t attn_smem = QTILE_H + 2u * TILE_H;    // 87040 B
    cudaFuncSetAttribute(gemm_f16<0,1>, cudaFuncAttributeMaxDynamicSharedMemorySize, (int)gemm_smem);
    cudaFuncSetAttribute(gemm_f16<1,0>, cudaFuncAttributeMaxDynamicSharedMemorySize, (int)gemm_smem);
    cudaFuncSetAttribute(attn_f16,      cudaFuncAttributeMaxDynamicSharedMemorySize, (int)attn_smem);

    gemm_f16<0,1><<<M / 128, 256, gemm_smem>>>(x, Wq, bq, nullptr, q, 0);
    gemm_f16<0,1><<<M / 128, 256, gemm_smem>>>(x, Wk, bk, nullptr, k, 0);
    gemm_f16<0,1><<<M / 128, 256, gemm_smem>>>(x, Wv, bv, nullptr, v, 0);

    dim3 ag(N_ / 64, B_);
    attn_f16<<<ag, 128, attn_smem>>>(q, k, v, adj, x, att);

    // FFN: h(fp16) = relu(att @ W1^T + b1); out = relu(h @ W2^T + b2) + att
    gemm_f16<0,1><<<M / 128, 256, gemm_smem>>>(att, W1, b1, nullptr, hbuf, 1);
    gemm_f16<1,0><<<M / 128, 256, gemm_smem>>>(hbuf, W2, b2, att, out, 1);
}

// round 15
// speedup vs baseline: 1.0102x; 1.0008x over previous
#include <cuda_runtime.h>
#include <cuda_fp16.h>
#include <cstdint>
#include <math.h>

#define B_ 4
#define N_ 4096
#define D_ 128
#define HS 136                    // halves per smem row (272B stride)
#define TILE_H (128u * HS * 2u)   // 34816 B per 128-row fp16 tile
#define QTILE_H (64u * HS * 2u)   // 17408 B per 64-row fp16 tile
#define NT (N_ / 128)

// ---------------- scratch (device globals; no runtime allocation) ----------
__device__ __half g_q[B_ * N_ * D_];
__device__ __half g_k[B_ * N_ * D_];
__device__ __half g_v[B_ * N_ * D_];
__device__ float  g_att[B_ * N_ * D_];
__device__ __half g_h[B_ * N_ * D_];

// ======================= helpers ===========================================
__device__ __forceinline__ uint32_t smem_u32(const void* p) {
    uint32_t a;
    asm("{ .reg .u64 t; cvta.to.shared.u64 t, %1; cvt.u32.u64 %0, t; }"
        : "=r"(a) : "l"(p));
    return a;
}

__device__ __forceinline__ float ex2f(float x) {
    float r;
    asm("ex2.approx.ftz.f32 %0, %1;" : "=f"(r) : "f"(x));
    return r;
}

__device__ __forceinline__ uint32_t f2h2(float a, float b) {
    __half2 h = __floats2half2_rn(a, b);
    return *reinterpret_cast<uint32_t*>(&h);
}

__device__ __forceinline__ void sts64(uint32_t addr, uint32_t lo, uint32_t hi) {
    asm volatile("st.shared.v2.b32 [%0], {%1,%2};" :: "r"(addr), "r"(lo), "r"(hi) : "memory");
}
__device__ __forceinline__ void sts128u(uint32_t addr, uint4 v) {
    asm volatile("st.shared.v4.b32 [%0], {%1,%2,%3,%4};"
        :: "r"(addr), "r"(v.x), "r"(v.y), "r"(v.z), "r"(v.w) : "memory");
}

__device__ __forceinline__ void cp16(uint32_t dst, const void* src) {
    asm volatile("cp.async.cg.shared.global [%0], [%1], 16;"
        :: "r"(dst), "l"(src) : "memory");
}
#define CP_COMMIT() asm volatile("cp.async.commit_group;" ::: "memory")
#define CP_WAIT0()  asm volatile("cp.async.wait_group 0;" ::: "memory")

__device__ __forceinline__ void ldsm_x4(uint32_t& r0, uint32_t& r1, uint32_t& r2, uint32_t& r3,
                                        uint32_t addr) {
    asm volatile("ldmatrix.sync.aligned.m8n8.x4.shared.b16 {%0,%1,%2,%3}, [%4];"
        : "=r"(r0), "=r"(r1), "=r"(r2), "=r"(r3) : "r"(addr));
}
__device__ __forceinline__ void ldsm_x4_t(uint32_t& r0, uint32_t& r1, uint32_t& r2, uint32_t& r3,
                                          uint32_t addr) {
    asm volatile("ldmatrix.sync.aligned.m8n8.x4.trans.shared.b16 {%0,%1,%2,%3}, [%4];"
        : "=r"(r0), "=r"(r1), "=r"(r2), "=r"(r3) : "r"(addr));
}

// D(16x8,f32) += A(16x16,f16 row) * B(16x8,f16 col)
__device__ __forceinline__ void mma_f16(float* d,
                                        uint32_t a0, uint32_t a1, uint32_t a2, uint32_t a3,
                                        uint32_t b0, uint32_t b1) {
    asm volatile(
        "mma.sync.aligned.m16n8k16.row.col.f32.f16.f16.f32 "
        "{%0,%1,%2,%3}, {%4,%5,%6,%7}, {%8,%9}, {%0,%1,%2,%3};"
        : "+f"(d[0]), "+f"(d[1]), "+f"(d[2]), "+f"(d[3])
        : "r"(a0), "r"(a1), "r"(a2), "r"(a3), "r"(b0), "r"(b1));
}

// ---------------------------------------------------------------------------
// fp16 flash attention, FA2 register-P, q-tile 64 / 4 warps / 2 CTAs per SM:
// each warp: 16 q-rows x full 128 kv. Single-buffered K/V (co-resident CTA
// hides the load wait). Fixed-shift softmax (C=3). Grid (N/64, B).
// Smem: Qh(64r) | K | V = 17408 + 2*34816 = 87040 B -> 2 CTAs/SM.
// ---------------------------------------------------------------------------
__global__ __launch_bounds__(128, 2) void attn_f16(
    const __half* __restrict__ Q, const __half* __restrict__ K,
    const __half* __restrict__ V, const float* __restrict__ adj,
    const float* __restrict__ X, float* __restrict__ Out)
{
    extern __shared__ __align__(16) char smraw[];
    const uint32_t Qb = smem_u32(smraw);
    const uint32_t Kb = Qb + QTILE_H;
    const uint32_t Vb = Kb + TILE_H;

    const int tid  = threadIdx.x;
    const int wid  = tid >> 5;      // 0..3 -> q rows [16*wid, 16*wid+16)
    const int lane = tid & 31;
    const int gq   = lane >> 2;
    const int tq   = lane & 3;
    const int lr   = lane & 7;
    const int g8   = lane >> 3;
    const int b    = blockIdx.y;
    const int q0   = blockIdx.x * 64;

    // ldmatrix per-lane address components (validated R6/R8/R9)
    const int arow = lr + ((g8 & 1) ? 8 : 0);   // A-type (Q)
    const int acol = (g8 & 2) ? 8 : 0;
    const int brow = lr + ((g8 & 2) ? 8 : 0);   // B-type (K)
    const int bcol = (g8 & 1) ? 8 : 0;
    const int vrow = lr + ((g8 & 1) ? 8 : 0);   // B-trans (V)
    const int vcol = (g8 & 2) ? 8 : 0;

    // ---- prologue: cp.async Q (64 rows) ----
    {
        const __half* Qg = Q + ((size_t)b * N_ + q0) * D_;
#pragma unroll
        for (int it = 0; it < 8; ++it) {
            int idx = tid + it * 128;          // 1024 16B-chunks
            int r = idx >> 4, c = idx & 15;
            cp16(Qb + (uint32_t)(r * HS + c * 8) * 2u, Qg + (size_t)r * D_ + c * 8);
        }
    }
    CP_COMMIT();

    const float scaleL = 0.088388347648318447f * 1.4426950408889634f;  // scale*log2e
    const float LOG2E  = 1.4426950408889634f;
    const float C      = 3.0f;

    const int tr0 = q0 + wid * 16 + gq;   // global q row of c0/c1
    const int tr1 = tr0 + 8;              // global q row of c2/c3

    float lsum0 = 0.f, lsum1 = 0.f;
    float Oacc[16][4];
#pragma unroll
    for (int nt = 0; nt < 16; ++nt)
#pragma unroll
        for (int j = 0; j < 4; ++j) Oacc[nt][j] = 0.f;

    for (int ct = 0; ct < NT; ++ct) {
        // ---- load this iter's K/V (single buffer; co-CTA hides the wait) ----
        {
            const __half* Kg = K + ((size_t)b * N_ + ct * 128) * D_;
            const __half* Vg = V + ((size_t)b * N_ + ct * 128) * D_;
#pragma unroll
            for (int it = 0; it < 16; ++it) {
                int idx = tid + it * 128;      // 2048 16B-chunks per tile
                int r = idx >> 4, c = idx & 15;
                uint32_t off = (uint32_t)(r * HS + c * 8) * 2u;
                const size_t gsrc = (size_t)r * D_ + c * 8;
                cp16(Kb + off, Kg + gsrc);
                cp16(Vb + off, Vg + gsrc);
            }
        }
        CP_COMMIT();
        CP_WAIT0();
        __syncthreads();

        // ---- MMA1: S = Q @ K^T  (warp tile 16 q x 128 kv) ----
        float Sacc[16][4];
#pragma unroll
        for (int nt = 0; nt < 16; ++nt)
#pragma unroll
            for (int j = 0; j < 4; ++j) Sacc[nt][j] = 0.f;

#pragma unroll
        for (int ks = 0; ks < 8; ++ks) {
            uint32_t qa0, qa1, qa2, qa3;
            ldsm_x4(qa0, qa1, qa2, qa3,
                    Qb + (uint32_t)((wid * 16 + arow) * HS + ks * 16 + acol) * 2u);
#pragma unroll
            for (int np = 0; np < 8; ++np) {
                uint32_t r0, r1, r2, r3;
                ldsm_x4(r0, r1, r2, r3,
                        Kb + (uint32_t)((np * 16 + brow) * HS + ks * 16 + bcol) * 2u);
                mma_f16(Sacc[np * 2],     qa0, qa1, qa2, qa3, r0, r1);
                mma_f16(Sacc[np * 2 + 1], qa0, qa1, qa2, qa3, r2, r3);
            }
        }

        // ---- softmax (fixed shift), P packed to half2 in registers ----
        uint32_t ph[16][2];
#pragma unroll
        for (int nt = 0; nt < 16; ++nt) {
            int cg = ct * 128 + nt * 8 + 2 * tq;
            float2 aj0 = *reinterpret_cast<const float2*>(adj + (size_t)tr0 * N_ + cg);
            float2 aj1 = *reinterpret_cast<const float2*>(adj + (size_t)tr1 * N_ + cg);
            float p0 = ex2f(fmaf(Sacc[nt][0], scaleL,
                                 (aj0.x + ((tr0 == cg)     ? 1.f : 0.f) - C) * LOG2E));
            float p1 = ex2f(fmaf(Sacc[nt][1], scaleL,
                                 (aj0.y + ((tr0 == cg + 1) ? 1.f : 0.f) - C) * LOG2E));
            float p2 = ex2f(fmaf(Sacc[nt][2], scaleL,
                                 (aj1.x + ((tr1 == cg)     ? 1.f : 0.f) - C) * LOG2E));
            float p3 = ex2f(fmaf(Sacc[nt][3], scaleL,
                                 (aj1.y + ((tr1 == cg + 1) ? 1.f : 0.f) - C) * LOG2E));
            lsum0 += p0 + p1;
            lsum1 += p2 + p3;
            ph[nt][0] = f2h2(p0, p1);   // rows gq   : MMA2 A-frag a0/a2
            ph[nt][1] = f2h2(p2, p3);   // rows gq+8 : MMA2 A-frag a1/a3
        }

        // ---- MMA2: O += P(regs) @ V  (k = 128 kv, n = 128 d) ----
#pragma unroll
        for (int kk = 0; kk < 8; ++kk) {
            uint32_t a0 = ph[2 * kk][0];
            uint32_t a1 = ph[2 * kk][1];
            uint32_t a2 = ph[2 * kk + 1][0];
            uint32_t a3 = ph[2 * kk + 1][1];
#pragma unroll
            for (int np = 0; np < 8; ++np) {
                uint32_t r0, r1, r2, r3;
                ldsm_x4_t(r0, r1, r2, r3,
                          Vb + (uint32_t)((kk * 16 + vrow) * HS + np * 16 + vcol) * 2u);
                mma_f16(Oacc[np * 2],     a0, a1, a2, a3, r0, r1);
                mma_f16(Oacc[np * 2 + 1], a0, a1, a2, a3, r2, r3);
            }
        }

        __syncthreads();   // all warps done with Kb/Vb before next overwrite
    }

    // ---- epilogue: intra-warp l reduction, out = relu(O/l) + x ----
    lsum0 += __shfl_xor_sync(0xffffffffu, lsum0, 1);
    lsum0 += __shfl_xor_sync(0xffffffffu, lsum0, 2);
    lsum1 += __shfl_xor_sync(0xffffffffu, lsum1, 1);
    lsum1 += __shfl_xor_sync(0xffffffffu, lsum1, 2);
    const float linv0 = 1.f / lsum0;
    const float linv1 = 1.f / lsum1;

#pragma unroll
    for (int nt = 0; nt < 16; ++nt) {
        int col = nt * 8 + 2 * tq;
        size_t base0 = ((size_t)b * N_ + tr0) * D_ + col;
        size_t base1 = ((size_t)b * N_ + tr1) * D_ + col;
        float2 x0 = *reinterpret_cast<const float2*>(X + base0);
        float2 x1 = *reinterpret_cast<const float2*>(X + base1);
        float2 o0, o1;
        o0.x = fmaxf(Oacc[nt][0] * linv0, 0.f) + x0.x;
        o0.y = fmaxf(Oacc[nt][1] * linv0, 0.f) + x0.y;
        o1.x = fmaxf(Oacc[nt][2] * linv1, 0.f) + x1.x;
        o1.y = fmaxf(Oacc[nt][3] * linv1, 0.f) + x1.y;
        *reinterpret_cast<float2*>(Out + base0) = o0;
        *reinterpret_cast<float2*>(Out + base1) = o1;
    }
}

// ---------------------------------------------------------------------------
// fp16 tensor GEMM: Y[M,128] = act(X[M,128] @ W^T[128,128] + b) (+ resid)
// Compile-time specialized on input/output dtype (validated R11/R12).
// 256 thr = 8 warps, 4x2 grid, CTA tile 128x128, K=128.
// ---------------------------------------------------------------------------
template <int IN_HALF, int OUT_HALF>
__global__ __launch_bounds__(256) void gemm_f16(
    const void* __restrict__ Xv, const float* __restrict__ W,
    const float* __restrict__ bias, const float* __restrict__ resid,
    void* __restrict__ Yv, int do_relu)
{
    extern __shared__ __align__(16) char smraw[];
    const uint32_t Xb = smem_u32(smraw);
    const uint32_t Wb = Xb + TILE_H;

    const int tid  = threadIdx.x;
    const int wid  = tid >> 5;
    const int lane = tid & 31;
    const int w_m  = wid & 3;
    const int w_n  = wid >> 2;
    const int gq   = lane >> 2;
    const int tq   = lane & 3;
    const int lr   = lane & 7;
    const int g8   = lane >> 3;
    const int row0 = blockIdx.x * 128;

    const int arow = lr + ((g8 & 1) ? 8 : 0);
    const int acol = (g8 & 2) ? 8 : 0;
    const int brow = lr + ((g8 & 2) ? 8 : 0);
    const int bcol = (g8 & 1) ? 8 : 0;

    // ---- stage W (fp32 -> fp16) ----
    {
        const float4* Wg = reinterpret_cast<const float4*>(W);
#pragma unroll
        for (int it = 0; it < 16; ++it) {
            int idx = tid + it * 256;
            int r = idx >> 5, c4 = idx & 31;
            float4 w4 = Wg[idx];
            sts64(Wb + (uint32_t)(r * HS + c4 * 4) * 2u, f2h2(w4.x, w4.y), f2h2(w4.z, w4.w));
        }
    }
    // ---- stage X ----
    if (IN_HALF) {
        const uint4* Xg = reinterpret_cast<const uint4*>(
            reinterpret_cast<const __half*>(Xv) + (size_t)row0 * D_);
#pragma unroll
        for (int it = 0; it < 8; ++it) {
            int idx = tid + it * 256;          // 2048 16B chunks = 128 rows x 16
            int r = idx >> 4, c = idx & 15;
            sts128u(Xb + (uint32_t)(r * HS + c * 8) * 2u, Xg[r * 16 + c]);
        }
    } else {
        const float4* Xg = reinterpret_cast<const float4*>(
            reinterpret_cast<const float*>(Xv) + (size_t)row0 * D_);
#pragma unroll
        for (int it = 0; it < 16; ++it) {
            int idx = tid + it * 256;
            int r = idx >> 5, c4 = idx & 31;
            float4 x4 = Xg[idx];
            sts64(Xb + (uint32_t)(r * HS + c4 * 4) * 2u, f2h2(x4.x, x4.y), f2h2(x4.z, x4.w));
        }
    }
    __syncthreads();

    float acc[2][8][4];
#pragma unroll
    for (int mi = 0; mi < 2; ++mi)
#pragma unroll
        for (int nt = 0; nt < 8; ++nt)
#pragma unroll
            for (int j = 0; j < 4; ++j) acc[mi][nt][j] = 0.f;

#pragma unroll
    for (int ks = 0; ks < 8; ++ks) {
        uint32_t xa[2][4];
#pragma unroll
        for (int mi = 0; mi < 2; ++mi)
            ldsm_x4(xa[mi][0], xa[mi][1], xa[mi][2], xa[mi][3],
                    Xb + (uint32_t)((w_m * 32 + mi * 16 + arow) * HS + ks * 16 + acol) * 2u);
#pragma unroll
        for (int np = 0; np < 4; ++np) {
            uint32_t r0, r1, r2, r3;
            ldsm_x4(r0, r1, r2, r3,
                    Wb + (uint32_t)((w_n * 64 + np * 16 + brow) * HS + ks * 16 + bcol) * 2u);
#pragma unroll
            for (int mi = 0; mi < 2; ++mi) {
                mma_f16(acc[mi][np * 2],     xa[mi][0], xa[mi][1], xa[mi][2], xa[mi][3], r0, r1);
                mma_f16(acc[mi][np * 2 + 1], xa[mi][0], xa[mi][1], xa[mi][2], xa[mi][3], r2, r3);
            }
        }
    }

#pragma unroll
    for (int mi = 0; mi < 2; ++mi)
#pragma unroll
        for (int hi = 0; hi < 2; ++hi) {
            const int row = row0 + w_m * 32 + mi * 16 + hi * 8 + gq;
#pragma unroll
            for (int nt = 0; nt < 8; ++nt) {
                int col = w_n * 64 + nt * 8 + 2 * tq;
                float2 bb = *reinterpret_cast<const float2*>(bias + col);
                float v0 = acc[mi][nt][hi * 2]     + bb.x;
                float v1 = acc[mi][nt][hi * 2 + 1] + bb.y;
                if (do_relu) { v0 = fmaxf(v0, 0.f); v1 = fmaxf(v1, 0.f); }
                size_t base = (size_t)row * D_ + col;
                if (resid) {
                    float2 r2 = *reinterpret_cast<const float2*>(resid + base);
                    v0 += r2.x; v1 += r2.y;
                }
                if (OUT_HALF) {
                    *reinterpret_cast<uint32_t*>(reinterpret_cast<__half*>(Yv) + base) =
                        f2h2(v0, v1);
                } else {
                    *reinterpret_cast<float2*>(reinterpret_cast<float*>(Yv) + base) =
                        make_float2(v0, v1);
                }
            }
        }
}

// ---------------------------------------------------------------------------
extern "C" void kernel_launch(void* const* d_in, const int* in_sizes, int n_in,
                              void* d_out, int out_size)
{
    const float* x   = (const float*)d_in[0];
    const float* adj = (const float*)d_in[1];
    const float* Wq  = (const float*)d_in[2];
    const float* bq  = (const float*)d_in[3];
    const float* Wk  = (const float*)d_in[4];
    const float* bk  = (const float*)d_in[5];
    const float* Wv  = (const float*)d_in[6];
    const float* bv  = (const float*)d_in[7];
    const float* W1  = (const float*)d_in[8];
    const float* b1  = (const float*)d_in[9];
    const float* W2  = (const float*)d_in[10];
    const float* b2  = (const float*)d_in[11];
    float* out = (float*)d_out;

    __half *q, *k, *v, *hbuf;
    float *att;
    cudaGetSymbolAddress((void**)&q,    g_q);
    cudaGetSymbolAddress((void**)&k,    g_k);
    cudaGetSymbolAddress((void**)&v,    g_v);
    cudaGetSymbolAddress((void**)&att,  g_att);
    cudaGetSymbolAddress((void**)&hbuf, g_h);

    const int M = B_ * N_;
    const size_t gemm_smem = 2u * TILE_H;              // 69632 B
    const size_t attn_smem = QTILE_H + 2u * TILE_H;    // 87040 B
    cudaFuncSetAttribute(gemm_f16<0,1>, cudaFuncAttributeMaxDynamicSharedMemorySize, (int)gemm_smem);
    cudaFuncSetAttribute(gemm_f16<1,0>, cudaFuncAttributeMaxDynamicSharedMemorySize, (int)gemm_smem);
    cudaFuncSetAttribute(attn_f16,      cudaFuncAttributeMaxDynamicSharedMemorySize, (int)attn_smem);

    gemm_f16<0,1><<<M / 128, 256, gemm_smem>>>(x, Wq, bq, nullptr, q, 0);
    gemm_f16<0,1><<<M / 128, 256, gemm_smem>>>(x, Wk, bk, nullptr, k, 0);
    gemm_f16<0,1><<<M / 128, 256, gemm_smem>>>(x, Wv, bv, nullptr, v, 0);

    dim3 ag(N_ / 64, B_);
    attn_f16<<<ag, 128, attn_smem>>>(q, k, v, adj, x, att);

    // FFN: h(fp16) = relu(att @ W1^T + b1); out = relu(h @ W2^T + b2) + att
    gemm_f16<0,1><<<M / 128, 256, gemm_smem>>>(att, W1, b1, nullptr, hbuf, 1);
    gemm_f16<1,0><<<M / 128, 256, gemm_smem>>>(hbuf, W2, b2, att, out, 1);
}

// round 16
// speedup vs baseline: 1.1311x; 1.1198x over previous
#include <cuda_runtime.h>
#include <cuda_fp16.h>
#include <cstdint>
#include <math.h>

#define B_ 4
#define N_ 4096
#define D_ 128
#define HS 136                    // halves per smem row (272B stride)
#define TILE_H (128u * HS * 2u)   // 34816 B per 128-row fp16 tile
#define NT (N_ / 128)

// ---------------- scratch (device globals; no runtime allocation) ----------
__device__ __half g_q[B_ * N_ * D_];
__device__ __half g_k[B_ * N_ * D_];
__device__ __half g_v[B_ * N_ * D_];
__device__ float  g_att[B_ * N_ * D_];

// ======================= helpers ===========================================
__device__ __forceinline__ uint32_t smem_u32(const void* p) {
    uint32_t a;
    asm("{ .reg .u64 t; cvta.to.shared.u64 t, %1; cvt.u32.u64 %0, t; }"
        : "=r"(a) : "l"(p));
    return a;
}

__device__ __forceinline__ float ex2f(float x) {
    float r;
    asm("ex2.approx.ftz.f32 %0, %1;" : "=f"(r) : "f"(x));
    return r;
}

__device__ __forceinline__ uint32_t f2h2(float a, float b) {
    __half2 h = __floats2half2_rn(a, b);
    return *reinterpret_cast<uint32_t*>(&h);
}

__device__ __forceinline__ void sts64(uint32_t addr, uint32_t lo, uint32_t hi) {
    asm volatile("st.shared.v2.b32 [%0], {%1,%2};" :: "r"(addr), "r"(lo), "r"(hi) : "memory");
}
__device__ __forceinline__ void sts32u(uint32_t addr, uint32_t v) {
    asm volatile("st.shared.b32 [%0], %1;" :: "r"(addr), "r"(v) : "memory");
}

__device__ __forceinline__ void cp16(uint32_t dst, const void* src) {
    asm volatile("cp.async.cg.shared.global [%0], [%1], 16;"
        :: "r"(dst), "l"(src) : "memory");
}
#define CP_COMMIT() asm volatile("cp.async.commit_group;" ::: "memory")
#define CP_WAIT0()  asm volatile("cp.async.wait_group 0;" ::: "memory")

__device__ __forceinline__ void ldsm_x4(uint32_t& r0, uint32_t& r1, uint32_t& r2, uint32_t& r3,
                                        uint32_t addr) {
    asm volatile("ldmatrix.sync.aligned.m8n8.x4.shared.b16 {%0,%1,%2,%3}, [%4];"
        : "=r"(r0), "=r"(r1), "=r"(r2), "=r"(r3) : "r"(addr));
}
__device__ __forceinline__ void ldsm_x4_t(uint32_t& r0, uint32_t& r1, uint32_t& r2, uint32_t& r3,
                                          uint32_t addr) {
    asm volatile("ldmatrix.sync.aligned.m8n8.x4.trans.shared.b16 {%0,%1,%2,%3}, [%4];"
        : "=r"(r0), "=r"(r1), "=r"(r2), "=r"(r3) : "r"(addr));
}

// D(16x8,f32) += A(16x16,f16 row) * B(16x8,f16 col)
__device__ __forceinline__ void mma_f16(float* d,
                                        uint32_t a0, uint32_t a1, uint32_t a2, uint32_t a3,
                                        uint32_t b0, uint32_t b1) {
    asm volatile(
        "mma.sync.aligned.m16n8k16.row.col.f32.f16.f16.f32 "
        "{%0,%1,%2,%3}, {%4,%5,%6,%7}, {%8,%9}, {%0,%1,%2,%3};"
        : "+f"(d[0]), "+f"(d[1]), "+f"(d[2]), "+f"(d[3])
        : "r"(a0), "r"(a1), "r"(a2), "r"(a3), "r"(b0), "r"(b1));
}

// ---------------------------------------------------------------------------
// fp16 flash attention, FA2 structure — EXACT R12 kernel (measured 167us):
// 8 warps, each 16 q-rows x full 128 kv. P stays in registers.
// Fixed-shift softmax (C=3). One __syncthreads per kv iteration.
// Smem: Qh | K0 | V0 | K1 | V1 = 5 * 34816 B (cp.async double-buffered K/V)
// ---------------------------------------------------------------------------
__global__ __launch_bounds__(256, 1) void attn_f16(
    const __half* __restrict__ Q, const __half* __restrict__ K,
    const __half* __restrict__ V, const float* __restrict__ adj,
    const float* __restrict__ X, float* __restrict__ Out)
{
    extern __shared__ __align__(16) char smraw[];
    const uint32_t Qb = smem_u32(smraw);
    const uint32_t Kt[2] = { Qb + 1u * TILE_H, Qb + 3u * TILE_H };
    const uint32_t Vt[2] = { Qb + 2u * TILE_H, Qb + 4u * TILE_H };

    const int tid  = threadIdx.x;
    const int wid  = tid >> 5;      // 0..7 -> q rows [16*wid, 16*wid+16)
    const int lane = tid & 31;
    const int gq   = lane >> 2;
    const int tq   = lane & 3;
    const int lr   = lane & 7;
    const int g8   = lane >> 3;
    const int b    = blockIdx.y;
    const int q0   = blockIdx.x * 128;

    const int arow = lr + ((g8 & 1) ? 8 : 0);   // A-type (Q)
    const int acol = (g8 & 2) ? 8 : 0;
    const int brow = lr + ((g8 & 2) ? 8 : 0);   // B-type (K)
    const int bcol = (g8 & 1) ? 8 : 0;
    const int vrow = lr + ((g8 & 1) ? 8 : 0);   // B-trans (V)
    const int vcol = (g8 & 2) ? 8 : 0;

    // ---- prologue: cp.async Q + K0 + V0 ----
    {
        const __half* Qg = Q + ((size_t)b * N_ + q0) * D_;
        const __half* Kg = K + ((size_t)b * N_) * D_;
        const __half* Vg = V + ((size_t)b * N_) * D_;
#pragma unroll
        for (int it = 0; it < 8; ++it) {
            int idx = tid + it * 256;          // 2048 16B-chunks per tile
            int r = idx >> 4, c = idx & 15;
            uint32_t off = (uint32_t)(r * HS + c * 8) * 2u;
            const size_t gsrc = (size_t)r * D_ + c * 8;
            cp16(Qb    + off, Qg + gsrc);
            cp16(Kt[0] + off, Kg + gsrc);
            cp16(Vt[0] + off, Vg + gsrc);
        }
    }
    CP_COMMIT();
    CP_WAIT0();
    __syncthreads();

    const float scaleL = 0.088388347648318447f * 1.4426950408889634f;  // scale*log2e
    const float LOG2E  = 1.4426950408889634f;
    const float C      = 3.0f;

    const int tr0 = q0 + wid * 16 + gq;   // global q row of c0/c1
    const int tr1 = tr0 + 8;              // global q row of c2/c3

    float lsum0 = 0.f, lsum1 = 0.f;
    float Oacc[16][4];
#pragma unroll
    for (int nt = 0; nt < 16; ++nt)
#pragma unroll
        for (int j = 0; j < 4; ++j) Oacc[nt][j] = 0.f;

    for (int ct = 0; ct < NT; ++ct) {
        const uint32_t Kb = Kt[ct & 1];
        const uint32_t Vb = Vt[ct & 1];

        // ---- prefetch next K/V into the other buffer (overlaps compute) ----
        if (ct + 1 < NT) {
            const __half* Kg = K + ((size_t)b * N_ + (ct + 1) * 128) * D_;
            const __half* Vg = V + ((size_t)b * N_ + (ct + 1) * 128) * D_;
            const uint32_t kd = Kt[(ct + 1) & 1];
            const uint32_t vd = Vt[(ct + 1) & 1];
#pragma unroll
            for (int it = 0; it < 8; ++it) {
                int idx = tid + it * 256;
                int r = idx >> 4, c = idx & 15;
                uint32_t off = (uint32_t)(r * HS + c * 8) * 2u;
                const size_t gsrc = (size_t)r * D_ + c * 8;
                cp16(kd + off, Kg + gsrc);
                cp16(vd + off, Vg + gsrc);
            }
            CP_COMMIT();
        }

        // ---- MMA1: S = Q @ K^T  (warp tile 16 q x 128 kv) ----
        float Sacc[16][4];
#pragma unroll
        for (int nt = 0; nt < 16; ++nt)
#pragma unroll
            for (int j = 0; j < 4; ++j) Sacc[nt][j] = 0.f;

#pragma unroll
        for (int ks = 0; ks < 8; ++ks) {
            uint32_t qa0, qa1, qa2, qa3;
            ldsm_x4(qa0, qa1, qa2, qa3,
                    Qb + (uint32_t)((wid * 16 + arow) * HS + ks * 16 + acol) * 2u);
#pragma unroll
            for (int np = 0; np < 8; ++np) {
                uint32_t r0, r1, r2, r3;
                ldsm_x4(r0, r1, r2, r3,
                        Kb + (uint32_t)((np * 16 + brow) * HS + ks * 16 + bcol) * 2u);
                mma_f16(Sacc[np * 2],     qa0, qa1, qa2, qa3, r0, r1);
                mma_f16(Sacc[np * 2 + 1], qa0, qa1, qa2, qa3, r2, r3);
            }
        }

        // ---- softmax (fixed shift), P packed to half2 in registers ----
        uint32_t ph[16][2];
#pragma unroll
        for (int nt = 0; nt < 16; ++nt) {
            int cg = ct * 128 + nt * 8 + 2 * tq;
            float2 aj0 = *reinterpret_cast<const float2*>(adj + (size_t)tr0 * N_ + cg);
            float2 aj1 = *reinterpret_cast<const float2*>(adj + (size_t)tr1 * N_ + cg);
            float p0 = ex2f(fmaf(Sacc[nt][0], scaleL,
                                 (aj0.x + ((tr0 == cg)     ? 1.f : 0.f) - C) * LOG2E));
            float p1 = ex2f(fmaf(Sacc[nt][1], scaleL,
                                 (aj0.y + ((tr0 == cg + 1) ? 1.f : 0.f) - C) * LOG2E));
            float p2 = ex2f(fmaf(Sacc[nt][2], scaleL,
                                 (aj1.x + ((tr1 == cg)     ? 1.f : 0.f) - C) * LOG2E));
            float p3 = ex2f(fmaf(Sacc[nt][3], scaleL,
                                 (aj1.y + ((tr1 == cg + 1) ? 1.f : 0.f) - C) * LOG2E));
            lsum0 += p0 + p1;
            lsum1 += p2 + p3;
            ph[nt][0] = f2h2(p0, p1);   // rows gq   : MMA2 A-frag a0/a2
            ph[nt][1] = f2h2(p2, p3);   // rows gq+8 : MMA2 A-frag a1/a3
        }

        // ---- MMA2: O += P(regs) @ V  (k = 128 kv, n = 128 d) ----
#pragma unroll
        for (int kk = 0; kk < 8; ++kk) {
            uint32_t a0 = ph[2 * kk][0];
            uint32_t a1 = ph[2 * kk][1];
            uint32_t a2 = ph[2 * kk + 1][0];
            uint32_t a3 = ph[2 * kk + 1][1];
#pragma unroll
            for (int np = 0; np < 8; ++np) {
                uint32_t r0, r1, r2, r3;
                ldsm_x4_t(r0, r1, r2, r3,
                          Vb + (uint32_t)((kk * 16 + vrow) * HS + np * 16 + vcol) * 2u);
                mma_f16(Oacc[np * 2],     a0, a1, a2, a3, r0, r1);
                mma_f16(Oacc[np * 2 + 1], a0, a1, a2, a3, r2, r3);
            }
        }

        CP_WAIT0();        // next K/V landed (had all of compute to arrive)
        __syncthreads();   // all warps done with this iter's buffers
    }

    // ---- epilogue: intra-warp l reduction, out = relu(O/l) + x ----
    lsum0 += __shfl_xor_sync(0xffffffffu, lsum0, 1);
    lsum0 += __shfl_xor_sync(0xffffffffu, lsum0, 2);
    lsum1 += __shfl_xor_sync(0xffffffffu, lsum1, 1);
    lsum1 += __shfl_xor_sync(0xffffffffu, lsum1, 2);
    const float linv0 = 1.f / lsum0;
    const float linv1 = 1.f / lsum1;

#pragma unroll
    for (int nt = 0; nt < 16; ++nt) {
        int col = nt * 8 + 2 * tq;
        size_t base0 = ((size_t)b * N_ + tr0) * D_ + col;
        size_t base1 = ((size_t)b * N_ + tr1) * D_ + col;
        float2 x0 = *reinterpret_cast<const float2*>(X + base0);
        float2 x1 = *reinterpret_cast<const float2*>(X + base1);
        float2 o0, o1;
        o0.x = fmaxf(Oacc[nt][0] * linv0, 0.f) + x0.x;
        o0.y = fmaxf(Oacc[nt][1] * linv0, 0.f) + x0.y;
        o1.x = fmaxf(Oacc[nt][2] * linv1, 0.f) + x1.x;
        o1.y = fmaxf(Oacc[nt][3] * linv1, 0.f) + x1.y;
        *reinterpret_cast<float2*>(Out + base0) = o0;
        *reinterpret_cast<float2*>(Out + base1) = o1;
    }
}

// ---------------------------------------------------------------------------
// fp16 tensor GEMM (fp32 in, fp16 out) — EXACT R12 gemm_f16<0,1> (QKV).
// 256 thr = 8 warps, 4x2 grid, CTA tile 128x128, K=128.
// ---------------------------------------------------------------------------
__global__ __launch_bounds__(256) void gemm_proj(
    const float* __restrict__ X, const float* __restrict__ W,
    const float* __restrict__ bias, __half* __restrict__ Y)
{
    extern __shared__ __align__(16) char smraw[];
    const uint32_t Xb = smem_u32(smraw);
    const uint32_t Wb = Xb + TILE_H;

    const int tid  = threadIdx.x;
    const int wid  = tid >> 5;
    const int lane = tid & 31;
    const int w_m  = wid & 3;
    const int w_n  = wid >> 2;
    const int gq   = lane >> 2;
    const int tq   = lane & 3;
    const int lr   = lane & 7;
    const int g8   = lane >> 3;
    const int row0 = blockIdx.x * 128;

    const int arow = lr + ((g8 & 1) ? 8 : 0);
    const int acol = (g8 & 2) ? 8 : 0;
    const int brow = lr + ((g8 & 2) ? 8 : 0);
    const int bcol = (g8 & 1) ? 8 : 0;

    {
        const float4* Xg = reinterpret_cast<const float4*>(X + (size_t)row0 * D_);
        const float4* Wg = reinterpret_cast<const float4*>(W);
#pragma unroll
        for (int it = 0; it < 16; ++it) {
            int idx = tid + it * 256;
            int r = idx >> 5, c4 = idx & 31;
            uint32_t off = (uint32_t)(r * HS + c4 * 4) * 2u;
            float4 x4 = Xg[idx];
            sts64(Xb + off, f2h2(x4.x, x4.y), f2h2(x4.z, x4.w));
            float4 w4 = Wg[idx];
            sts64(Wb + off, f2h2(w4.x, w4.y), f2h2(w4.z, w4.w));
        }
    }
    __syncthreads();

    float acc[2][8][4];
#pragma unroll
    for (int mi = 0; mi < 2; ++mi)
#pragma unroll
        for (int nt = 0; nt < 8; ++nt)
#pragma unroll
            for (int j = 0; j < 4; ++j) acc[mi][nt][j] = 0.f;

#pragma unroll
    for (int ks = 0; ks < 8; ++ks) {
        uint32_t xa[2][4];
#pragma unroll
        for (int mi = 0; mi < 2; ++mi)
            ldsm_x4(xa[mi][0], xa[mi][1], xa[mi][2], xa[mi][3],
                    Xb + (uint32_t)((w_m * 32 + mi * 16 + arow) * HS + ks * 16 + acol) * 2u);
#pragma unroll
        for (int np = 0; np < 4; ++np) {
            uint32_t r0, r1, r2, r3;
            ldsm_x4(r0, r1, r2, r3,
                    Wb + (uint32_t)((w_n * 64 + np * 16 + brow) * HS + ks * 16 + bcol) * 2u);
#pragma unroll
            for (int mi = 0; mi < 2; ++mi) {
                mma_f16(acc[mi][np * 2],     xa[mi][0], xa[mi][1], xa[mi][2], xa[mi][3], r0, r1);
                mma_f16(acc[mi][np * 2 + 1], xa[mi][0], xa[mi][1], xa[mi][2], xa[mi][3], r2, r3);
            }
        }
    }

#pragma unroll
    for (int mi = 0; mi < 2; ++mi)
#pragma unroll
        for (int hi = 0; hi < 2; ++hi) {
            const int row = row0 + w_m * 32 + mi * 16 + hi * 8 + gq;
#pragma unroll
            for (int nt = 0; nt < 8; ++nt) {
                int col = w_n * 64 + nt * 8 + 2 * tq;
                float2 bb = *reinterpret_cast<const float2*>(bias + col);
                float v0 = acc[mi][nt][hi * 2]     + bb.x;
                float v1 = acc[mi][nt][hi * 2 + 1] + bb.y;
                *reinterpret_cast<uint32_t*>(Y + (size_t)row * D_ + col) = f2h2(v0, v1);
            }
        }
}

// ---------------------------------------------------------------------------
// Fused FFN: out = relu( relu(att@W1^T + b1) @ W2^T + b2 ) + att
// h (fp16) lives in the X staging buffer between the two mainloops —
// identical rounding to the previous gmem round-trip, one launch instead of 2.
// Smem: Xb | W1b | W2b = 3 * 34816 = 104448 B. Grid 128 (1 CTA/SM, 1 wave).
// ---------------------------------------------------------------------------
__global__ __launch_bounds__(256) void gemm_ffn(
    const float* __restrict__ att,
    const float* __restrict__ W1, const float* __restrict__ b1,
    const float* __restrict__ W2, const float* __restrict__ b2,
    float* __restrict__ out)
{
    extern __shared__ __align__(16) char smraw[];
    const uint32_t Xb  = smem_u32(smraw);
    const uint32_t W1b = Xb + TILE_H;
    const uint32_t W2b = Xb + 2u * TILE_H;

    const int tid  = threadIdx.x;
    const int wid  = tid >> 5;
    const int lane = tid & 31;
    const int w_m  = wid & 3;
    const int w_n  = wid >> 2;
    const int gq   = lane >> 2;
    const int tq   = lane & 3;
    const int lr   = lane & 7;
    const int g8   = lane >> 3;
    const int row0 = blockIdx.x * 128;

    const int arow = lr + ((g8 & 1) ? 8 : 0);
    const int acol = (g8 & 2) ? 8 : 0;
    const int brow = lr + ((g8 & 2) ? 8 : 0);
    const int bcol = (g8 & 1) ? 8 : 0;

    // ---- stage att + W1 + W2 (fp32 -> fp16) ----
    {
        const float4* Xg  = reinterpret_cast<const float4*>(att + (size_t)row0 * D_);
        const float4* Wg1 = reinterpret_cast<const float4*>(W1);
        const float4* Wg2 = reinterpret_cast<const float4*>(W2);
#pragma unroll
        for (int it = 0; it < 16; ++it) {
            int idx = tid + it * 256;
            int r = idx >> 5, c4 = idx & 31;
            uint32_t off = (uint32_t)(r * HS + c4 * 4) * 2u;
            float4 x4 = Xg[idx];
            sts64(Xb + off, f2h2(x4.x, x4.y), f2h2(x4.z, x4.w));
            float4 w1 = Wg1[idx];
            sts64(W1b + off, f2h2(w1.x, w1.y), f2h2(w1.z, w1.w));
            float4 w2 = Wg2[idx];
            sts64(W2b + off, f2h2(w2.x, w2.y), f2h2(w2.z, w2.w));
        }
    }
    __syncthreads();

    float acc[2][8][4];

    // ================= pass 1: h = relu(att @ W1^T + b1) =================
#pragma unroll
    for (int mi = 0; mi < 2; ++mi)
#pragma unroll
        for (int nt = 0; nt < 8; ++nt)
#pragma unroll
            for (int j = 0; j < 4; ++j) acc[mi][nt][j] = 0.f;

#pragma unroll
    for (int ks = 0; ks < 8; ++ks) {
        uint32_t xa[2][4];
#pragma unroll
        for (int mi = 0; mi < 2; ++mi)
            ldsm_x4(xa[mi][0], xa[mi][1], xa[mi][2], xa[mi][3],
                    Xb + (uint32_t)((w_m * 32 + mi * 16 + arow) * HS + ks * 16 + acol) * 2u);
#pragma unroll
        for (int np = 0; np < 4; ++np) {
            uint32_t r0, r1, r2, r3;
            ldsm_x4(r0, r1, r2, r3,
                    W1b + (uint32_t)((w_n * 64 + np * 16 + brow) * HS + ks * 16 + bcol) * 2u);
#pragma unroll
            for (int mi = 0; mi < 2; ++mi) {
                mma_f16(acc[mi][np * 2],     xa[mi][0], xa[mi][1], xa[mi][2], xa[mi][3], r0, r1);
                mma_f16(acc[mi][np * 2 + 1], xa[mi][0], xa[mi][1], xa[mi][2], xa[mi][3], r2, r3);
            }
        }
    }
    __syncthreads();   // all warps done reading Xb (att) before h overwrites it

    // h -> Xb (fp16), same layout
#pragma unroll
    for (int mi = 0; mi < 2; ++mi)
#pragma unroll
        for (int hi = 0; hi < 2; ++hi) {
            const int rl = w_m * 32 + mi * 16 + hi * 8 + gq;
#pragma unroll
            for (int nt = 0; nt < 8; ++nt) {
                int col = w_n * 64 + nt * 8 + 2 * tq;
                float2 bb = *reinterpret_cast<const float2*>(b1 + col);
                float v0 = fmaxf(acc[mi][nt][hi * 2]     + bb.x, 0.f);
                float v1 = fmaxf(acc[mi][nt][hi * 2 + 1] + bb.y, 0.f);
                sts32u(Xb + (uint32_t)(rl * HS + col) * 2u, f2h2(v0, v1));
            }
        }
    __syncthreads();

    // ================= pass 2: out = relu(h @ W2^T + b2) + att ============
#pragma unroll
    for (int mi = 0; mi < 2; ++mi)
#pragma unroll
        for (int nt = 0; nt < 8; ++nt)
#pragma unroll
            for (int j = 0; j < 4; ++j) acc[mi][nt][j] = 0.f;

#pragma unroll
    for (int ks = 0; ks < 8; ++ks) {
        uint32_t xa[2][4];
#pragma unroll
        for (int mi = 0; mi < 2; ++mi)
            ldsm_x4(xa[mi][0], xa[mi][1], xa[mi][2], xa[mi][3],
                    Xb + (uint32_t)((w_m * 32 + mi * 16 + arow) * HS + ks * 16 + acol) * 2u);
#pragma unroll
        for (int np = 0; np < 4; ++np) {
            uint32_t r0, r1, r2, r3;
            ldsm_x4(r0, r1, r2, r3,
                    W2b + (uint32_t)((w_n * 64 + np * 16 + brow) * HS + ks * 16 + bcol) * 2u);
#pragma unroll
            for (int mi = 0; mi < 2; ++mi) {
                mma_f16(acc[mi][np * 2],     xa[mi][0], xa[mi][1], xa[mi][2], xa[mi][3], r0, r1);
                mma_f16(acc[mi][np * 2 + 1], xa[mi][0], xa[mi][1], xa[mi][2], xa[mi][3], r2, r3);
            }
        }
    }

#pragma unroll
    for (int mi = 0; mi < 2; ++mi)
#pragma unroll
        for (int hi = 0; hi < 2; ++hi) {
            const int row = row0 + w_m * 32 + mi * 16 + hi * 8 + gq;
#pragma unroll
            for (int nt = 0; nt < 8; ++nt) {
                int col = w_n * 64 + nt * 8 + 2 * tq;
                float2 bb = *reinterpret_cast<const float2*>(b2 + col);
                size_t base = (size_t)row * D_ + col;
                float2 r2 = *reinterpret_cast<const float2*>(att + base);
                float v0 = fmaxf(acc[mi][nt][hi * 2]     + bb.x, 0.f) + r2.x;
                float v1 = fmaxf(acc[mi][nt][hi * 2 + 1] + bb.y, 0.f) + r2.y;
                *reinterpret_cast<float2*>(out + base) = make_float2(v0, v1);
            }
        }
}

// ---------------------------------------------------------------------------
extern "C" void kernel_launch(void* const* d_in, const int* in_sizes, int n_in,
                              void* d_out, int out_size)
{
    const float* x   = (const float*)d_in[0];
    const float* adj = (const float*)d_in[1];
    const float* Wq  = (const float*)d_in[2];
    const float* bq  = (const float*)d_in[3];
    const float* Wk  = (const float*)d_in[4];
    const float* bk  = (const float*)d_in[5];
    const float* Wv  = (const float*)d_in[6];
    const float* bv  = (const float*)d_in[7];
    const float* W1  = (const float*)d_in[8];
    const float* b1  = (const float*)d_in[9];
    const float* W2  = (const float*)d_in[10];
    const float* b2  = (const float*)d_in[11];
    float* out = (float*)d_out;

    __half *q, *k, *v;
    float *att;
    cudaGetSymbolAddress((void**)&q,   g_q);
    cudaGetSymbolAddress((void**)&k,   g_k);
    cudaGetSymbolAddress((void**)&v,   g_v);
    cudaGetSymbolAddress((void**)&att, g_att);

    const int M = B_ * N_;
    const size_t proj_smem = 2u * TILE_H;   // 69632 B
    const size_t ffn_smem  = 3u * TILE_H;   // 104448 B
    const size_t attn_smem = 5u * TILE_H;   // 174080 B
    cudaFuncSetAttribute(gemm_proj, cudaFuncAttributeMaxDynamicSharedMemorySize, (int)proj_smem);
    cudaFuncSetAttribute(gemm_ffn,  cudaFuncAttributeMaxDynamicSharedMemorySize, (int)ffn_smem);
    cudaFuncSetAttribute(attn_f16,  cudaFuncAttributeMaxDynamicSharedMemorySize, (int)attn_smem);

    gemm_proj<<<M / 128, 256, proj_smem>>>(x, Wq, bq, q);
    gemm_proj<<<M / 128, 256, proj_smem>>>(x, Wk, bk, k);
    gemm_proj<<<M / 128, 256, proj_smem>>>(x, Wv, bv, v);

    dim3 ag(N_ / 128, B_);
    attn_f16<<<ag, 256, attn_smem>>>(q, k, v, adj, x, att);

    gemm_ffn<<<M / 128, 256, ffn_smem>>>(att, W1, b1, W2, b2, out);
}

// round 17
// speedup vs baseline: 1.1410x; 1.0087x over previous
#include <cuda_runtime.h>
#include <cuda_fp16.h>
#include <cstdint>
#include <math.h>

#define B_ 4
#define N_ 4096
#define D_ 128
#define HS 136                    // halves per smem row (272B stride)
#define TILE_H (128u * HS * 2u)   // 34816 B per 128-row fp16 tile
#define NT (N_ / 128)

// ---------------- scratch (device globals; no runtime allocation) ----------
__device__ __half g_q[B_ * N_ * D_];
__device__ __half g_k[B_ * N_ * D_];
__device__ __half g_v[B_ * N_ * D_];
__device__ float  g_att[B_ * N_ * D_];

// ======================= helpers ===========================================
__device__ __forceinline__ uint32_t smem_u32(const void* p) {
    uint32_t a;
    asm("{ .reg .u64 t; cvta.to.shared.u64 t, %1; cvt.u32.u64 %0, t; }"
        : "=r"(a) : "l"(p));
    return a;
}

__device__ __forceinline__ float ex2f(float x) {
    float r;
    asm("ex2.approx.ftz.f32 %0, %1;" : "=f"(r) : "f"(x));
    return r;
}

__device__ __forceinline__ uint32_t f2h2(float a, float b) {
    __half2 h = __floats2half2_rn(a, b);
    return *reinterpret_cast<uint32_t*>(&h);
}

__device__ __forceinline__ void sts64(uint32_t addr, uint32_t lo, uint32_t hi) {
    asm volatile("st.shared.v2.b32 [%0], {%1,%2};" :: "r"(addr), "r"(lo), "r"(hi) : "memory");
}
__device__ __forceinline__ void sts32u(uint32_t addr, uint32_t v) {
    asm volatile("st.shared.b32 [%0], %1;" :: "r"(addr), "r"(v) : "memory");
}

__device__ __forceinline__ void cp16(uint32_t dst, const void* src) {
    asm volatile("cp.async.cg.shared.global [%0], [%1], 16;"
        :: "r"(dst), "l"(src) : "memory");
}
#define CP_COMMIT() asm volatile("cp.async.commit_group;" ::: "memory")
#define CP_WAIT0()  asm volatile("cp.async.wait_group 0;" ::: "memory")

__device__ __forceinline__ void ldsm_x4(uint32_t& r0, uint32_t& r1, uint32_t& r2, uint32_t& r3,
                                        uint32_t addr) {
    asm volatile("ldmatrix.sync.aligned.m8n8.x4.shared.b16 {%0,%1,%2,%3}, [%4];"
        : "=r"(r0), "=r"(r1), "=r"(r2), "=r"(r3) : "r"(addr));
}
__device__ __forceinline__ void ldsm_x4_t(uint32_t& r0, uint32_t& r1, uint32_t& r2, uint32_t& r3,
                                          uint32_t addr) {
    asm volatile("ldmatrix.sync.aligned.m8n8.x4.trans.shared.b16 {%0,%1,%2,%3}, [%4];"
        : "=r"(r0), "=r"(r1), "=r"(r2), "=r"(r3) : "r"(addr));
}

// D(16x8,f32) += A(16x16,f16 row) * B(16x8,f16 col)
__device__ __forceinline__ void mma_f16(float* d,
                                        uint32_t a0, uint32_t a1, uint32_t a2, uint32_t a3,
                                        uint32_t b0, uint32_t b1) {
    asm volatile(
        "mma.sync.aligned.m16n8k16.row.col.f32.f16.f16.f32 "
        "{%0,%1,%2,%3}, {%4,%5,%6,%7}, {%8,%9}, {%0,%1,%2,%3};"
        : "+f"(d[0]), "+f"(d[1]), "+f"(d[2]), "+f"(d[3])
        : "r"(a0), "r"(a1), "r"(a2), "r"(a3), "r"(b0), "r"(b1));
}

// ---------------------------------------------------------------------------
// fp16 flash attention, FA2 structure — EXACT R12/R16 kernel (measured 167us):
// 8 warps, each 16 q-rows x full 128 kv. P stays in registers.
// Fixed-shift softmax (C=3). One __syncthreads per kv iteration.
// Smem: Qh | K0 | V0 | K1 | V1 = 5 * 34816 B (cp.async double-buffered K/V)
// ---------------------------------------------------------------------------
__global__ __launch_bounds__(256, 1) void attn_f16(
    const __half* __restrict__ Q, const __half* __restrict__ K,
    const __half* __restrict__ V, const float* __restrict__ adj,
    const float* __restrict__ X, float* __restrict__ Out)
{
    extern __shared__ __align__(16) char smraw[];
    const uint32_t Qb = smem_u32(smraw);
    const uint32_t Kt[2] = { Qb + 1u * TILE_H, Qb + 3u * TILE_H };
    const uint32_t Vt[2] = { Qb + 2u * TILE_H, Qb + 4u * TILE_H };

    const int tid  = threadIdx.x;
    const int wid  = tid >> 5;      // 0..7 -> q rows [16*wid, 16*wid+16)
    const int lane = tid & 31;
    const int gq   = lane >> 2;
    const int tq   = lane & 3;
    const int lr   = lane & 7;
    const int g8   = lane >> 3;
    const int b    = blockIdx.y;
    const int q0   = blockIdx.x * 128;

    const int arow = lr + ((g8 & 1) ? 8 : 0);   // A-type (Q)
    const int acol = (g8 & 2) ? 8 : 0;
    const int brow = lr + ((g8 & 2) ? 8 : 0);   // B-type (K)
    const int bcol = (g8 & 1) ? 8 : 0;
    const int vrow = lr + ((g8 & 1) ? 8 : 0);   // B-trans (V)
    const int vcol = (g8 & 2) ? 8 : 0;

    // ---- prologue: cp.async Q + K0 + V0 ----
    {
        const __half* Qg = Q + ((size_t)b * N_ + q0) * D_;
        const __half* Kg = K + ((size_t)b * N_) * D_;
        const __half* Vg = V + ((size_t)b * N_) * D_;
#pragma unroll
        for (int it = 0; it < 8; ++it) {
            int idx = tid + it * 256;          // 2048 16B-chunks per tile
            int r = idx >> 4, c = idx & 15;
            uint32_t off = (uint32_t)(r * HS + c * 8) * 2u;
            const size_t gsrc = (size_t)r * D_ + c * 8;
            cp16(Qb    + off, Qg + gsrc);
            cp16(Kt[0] + off, Kg + gsrc);
            cp16(Vt[0] + off, Vg + gsrc);
        }
    }
    CP_COMMIT();
    CP_WAIT0();
    __syncthreads();

    const float scaleL = 0.088388347648318447f * 1.4426950408889634f;  // scale*log2e
    const float LOG2E  = 1.4426950408889634f;
    const float C      = 3.0f;

    const int tr0 = q0 + wid * 16 + gq;   // global q row of c0/c1
    const int tr1 = tr0 + 8;              // global q row of c2/c3

    float lsum0 = 0.f, lsum1 = 0.f;
    float Oacc[16][4];
#pragma unroll
    for (int nt = 0; nt < 16; ++nt)
#pragma unroll
        for (int j = 0; j < 4; ++j) Oacc[nt][j] = 0.f;

    for (int ct = 0; ct < NT; ++ct) {
        const uint32_t Kb = Kt[ct & 1];
        const uint32_t Vb = Vt[ct & 1];

        // ---- prefetch next K/V into the other buffer (overlaps compute) ----
        if (ct + 1 < NT) {
            const __half* Kg = K + ((size_t)b * N_ + (ct + 1) * 128) * D_;
            const __half* Vg = V + ((size_t)b * N_ + (ct + 1) * 128) * D_;
            const uint32_t kd = Kt[(ct + 1) & 1];
            const uint32_t vd = Vt[(ct + 1) & 1];
#pragma unroll
            for (int it = 0; it < 8; ++it) {
                int idx = tid + it * 256;
                int r = idx >> 4, c = idx & 15;
                uint32_t off = (uint32_t)(r * HS + c * 8) * 2u;
                const size_t gsrc = (size_t)r * D_ + c * 8;
                cp16(kd + off, Kg + gsrc);
                cp16(vd + off, Vg + gsrc);
            }
            CP_COMMIT();
        }

        // ---- MMA1: S = Q @ K^T  (warp tile 16 q x 128 kv) ----
        float Sacc[16][4];
#pragma unroll
        for (int nt = 0; nt < 16; ++nt)
#pragma unroll
            for (int j = 0; j < 4; ++j) Sacc[nt][j] = 0.f;

#pragma unroll
        for (int ks = 0; ks < 8; ++ks) {
            uint32_t qa0, qa1, qa2, qa3;
            ldsm_x4(qa0, qa1, qa2, qa3,
                    Qb + (uint32_t)((wid * 16 + arow) * HS + ks * 16 + acol) * 2u);
#pragma unroll
            for (int np = 0; np < 8; ++np) {
                uint32_t r0, r1, r2, r3;
                ldsm_x4(r0, r1, r2, r3,
                        Kb + (uint32_t)((np * 16 + brow) * HS + ks * 16 + bcol) * 2u);
                mma_f16(Sacc[np * 2],     qa0, qa1, qa2, qa3, r0, r1);
                mma_f16(Sacc[np * 2 + 1], qa0, qa1, qa2, qa3, r2, r3);
            }
        }

        // ---- softmax (fixed shift), P packed to half2 in registers ----
        uint32_t ph[16][2];
#pragma unroll
        for (int nt = 0; nt < 16; ++nt) {
            int cg = ct * 128 + nt * 8 + 2 * tq;
            float2 aj0 = *reinterpret_cast<const float2*>(adj + (size_t)tr0 * N_ + cg);
            float2 aj1 = *reinterpret_cast<const float2*>(adj + (size_t)tr1 * N_ + cg);
            float p0 = ex2f(fmaf(Sacc[nt][0], scaleL,
                                 (aj0.x + ((tr0 == cg)     ? 1.f : 0.f) - C) * LOG2E));
            float p1 = ex2f(fmaf(Sacc[nt][1], scaleL,
                                 (aj0.y + ((tr0 == cg + 1) ? 1.f : 0.f) - C) * LOG2E));
            float p2 = ex2f(fmaf(Sacc[nt][2], scaleL,
                                 (aj1.x + ((tr1 == cg)     ? 1.f : 0.f) - C) * LOG2E));
            float p3 = ex2f(fmaf(Sacc[nt][3], scaleL,
                                 (aj1.y + ((tr1 == cg + 1) ? 1.f : 0.f) - C) * LOG2E));
            lsum0 += p0 + p1;
            lsum1 += p2 + p3;
            ph[nt][0] = f2h2(p0, p1);   // rows gq   : MMA2 A-frag a0/a2
            ph[nt][1] = f2h2(p2, p3);   // rows gq+8 : MMA2 A-frag a1/a3
        }

        // ---- MMA2: O += P(regs) @ V  (k = 128 kv, n = 128 d) ----
#pragma unroll
        for (int kk = 0; kk < 8; ++kk) {
            uint32_t a0 = ph[2 * kk][0];
            uint32_t a1 = ph[2 * kk][1];
            uint32_t a2 = ph[2 * kk + 1][0];
            uint32_t a3 = ph[2 * kk + 1][1];
#pragma unroll
            for (int np = 0; np < 8; ++np) {
                uint32_t r0, r1, r2, r3;
                ldsm_x4_t(r0, r1, r2, r3,
                          Vb + (uint32_t)((kk * 16 + vrow) * HS + np * 16 + vcol) * 2u);
                mma_f16(Oacc[np * 2],     a0, a1, a2, a3, r0, r1);
                mma_f16(Oacc[np * 2 + 1], a0, a1, a2, a3, r2, r3);
            }
        }

        CP_WAIT0();        // next K/V landed (had all of compute to arrive)
        __syncthreads();   // all warps done with this iter's buffers
    }

    // ---- epilogue: intra-warp l reduction, out = relu(O/l) + x ----
    lsum0 += __shfl_xor_sync(0xffffffffu, lsum0, 1);
    lsum0 += __shfl_xor_sync(0xffffffffu, lsum0, 2);
    lsum1 += __shfl_xor_sync(0xffffffffu, lsum1, 1);
    lsum1 += __shfl_xor_sync(0xffffffffu, lsum1, 2);
    const float linv0 = 1.f / lsum0;
    const float linv1 = 1.f / lsum1;

#pragma unroll
    for (int nt = 0; nt < 16; ++nt) {
        int col = nt * 8 + 2 * tq;
        size_t base0 = ((size_t)b * N_ + tr0) * D_ + col;
        size_t base1 = ((size_t)b * N_ + tr1) * D_ + col;
        float2 x0 = *reinterpret_cast<const float2*>(X + base0);
        float2 x1 = *reinterpret_cast<const float2*>(X + base1);
        float2 o0, o1;
        o0.x = fmaxf(Oacc[nt][0] * linv0, 0.f) + x0.x;
        o0.y = fmaxf(Oacc[nt][1] * linv0, 0.f) + x0.y;
        o1.x = fmaxf(Oacc[nt][2] * linv1, 0.f) + x1.x;
        o1.y = fmaxf(Oacc[nt][3] * linv1, 0.f) + x1.y;
        *reinterpret_cast<float2*>(Out + base0) = o0;
        *reinterpret_cast<float2*>(Out + base1) = o1;
    }
}

// ---------------------------------------------------------------------------
// Batched QKV projection: grid (M/128, 3); blockIdx.y selects {Wq,Wk,Wv}.
// Per-CTA work identical to R16's gemm_proj (69 KB smem, 8 warps) —
// only the 3 launches are merged into one.
// ---------------------------------------------------------------------------
__global__ __launch_bounds__(256) void gemm_qkv3(
    const float* __restrict__ X,
    const float* __restrict__ Wq, const float* __restrict__ bq,
    const float* __restrict__ Wk, const float* __restrict__ bk,
    const float* __restrict__ Wv, const float* __restrict__ bv,
    __half* __restrict__ Qo, __half* __restrict__ Ko, __half* __restrict__ Vo)
{
    extern __shared__ __align__(16) char smraw[];
    const uint32_t Xb = smem_u32(smraw);
    const uint32_t Wb = Xb + TILE_H;

    const int tid  = threadIdx.x;
    const int wid  = tid >> 5;
    const int lane = tid & 31;
    const int w_m  = wid & 3;
    const int w_n  = wid >> 2;
    const int gq   = lane >> 2;
    const int tq   = lane & 3;
    const int lr   = lane & 7;
    const int g8   = lane >> 3;
    const int row0 = blockIdx.x * 128;

    const float* W;
    const float* bias;
    __half* Y;
    if (blockIdx.y == 0)      { W = Wq; bias = bq; Y = Qo; }
    else if (blockIdx.y == 1) { W = Wk; bias = bk; Y = Ko; }
    else                      { W = Wv; bias = bv; Y = Vo; }

    const int arow = lr + ((g8 & 1) ? 8 : 0);
    const int acol = (g8 & 2) ? 8 : 0;
    const int brow = lr + ((g8 & 2) ? 8 : 0);
    const int bcol = (g8 & 1) ? 8 : 0;

    {
        const float4* Xg = reinterpret_cast<const float4*>(X + (size_t)row0 * D_);
        const float4* Wg = reinterpret_cast<const float4*>(W);
#pragma unroll
        for (int it = 0; it < 16; ++it) {
            int idx = tid + it * 256;
            int r = idx >> 5, c4 = idx & 31;
            uint32_t off = (uint32_t)(r * HS + c4 * 4) * 2u;
            float4 x4 = Xg[idx];
            sts64(Xb + off, f2h2(x4.x, x4.y), f2h2(x4.z, x4.w));
            float4 w4 = Wg[idx];
            sts64(Wb + off, f2h2(w4.x, w4.y), f2h2(w4.z, w4.w));
        }
    }
    __syncthreads();

    float acc[2][8][4];
#pragma unroll
    for (int mi = 0; mi < 2; ++mi)
#pragma unroll
        for (int nt = 0; nt < 8; ++nt)
#pragma unroll
            for (int j = 0; j < 4; ++j) acc[mi][nt][j] = 0.f;

#pragma unroll
    for (int ks = 0; ks < 8; ++ks) {
        uint32_t xa[2][4];
#pragma unroll
        for (int mi = 0; mi < 2; ++mi)
            ldsm_x4(xa[mi][0], xa[mi][1], xa[mi][2], xa[mi][3],
                    Xb + (uint32_t)((w_m * 32 + mi * 16 + arow) * HS + ks * 16 + acol) * 2u);
#pragma unroll
        for (int np = 0; np < 4; ++np) {
            uint32_t r0, r1, r2, r3;
            ldsm_x4(r0, r1, r2, r3,
                    Wb + (uint32_t)((w_n * 64 + np * 16 + brow) * HS + ks * 16 + bcol) * 2u);
#pragma unroll
            for (int mi = 0; mi < 2; ++mi) {
                mma_f16(acc[mi][np * 2],     xa[mi][0], xa[mi][1], xa[mi][2], xa[mi][3], r0, r1);
                mma_f16(acc[mi][np * 2 + 1], xa[mi][0], xa[mi][1], xa[mi][2], xa[mi][3], r2, r3);
            }
        }
    }

#pragma unroll
    for (int mi = 0; mi < 2; ++mi)
#pragma unroll
        for (int hi = 0; hi < 2; ++hi) {
            const int row = row0 + w_m * 32 + mi * 16 + hi * 8 + gq;
#pragma unroll
            for (int nt = 0; nt < 8; ++nt) {
                int col = w_n * 64 + nt * 8 + 2 * tq;
                float2 bb = *reinterpret_cast<const float2*>(bias + col);
                float v0 = acc[mi][nt][hi * 2]     + bb.x;
                float v1 = acc[mi][nt][hi * 2 + 1] + bb.y;
                *reinterpret_cast<uint32_t*>(Y + (size_t)row * D_ + col) = f2h2(v0, v1);
            }
        }
}

// ---------------------------------------------------------------------------
// Fused FFN: out = relu( relu(att@W1^T + b1) @ W2^T + b2 ) + att
// (EXACT R16 kernel — measured good)
// Smem: Xb | W1b | W2b = 3 * 34816 = 104448 B. Grid 128 (1 CTA/SM, 1 wave).
// ---------------------------------------------------------------------------
__global__ __launch_bounds__(256) void gemm_ffn(
    const float* __restrict__ att,
    const float* __restrict__ W1, const float* __restrict__ b1,
    const float* __restrict__ W2, const float* __restrict__ b2,
    float* __restrict__ out)
{
    extern __shared__ __align__(16) char smraw[];
    const uint32_t Xb  = smem_u32(smraw);
    const uint32_t W1b = Xb + TILE_H;
    const uint32_t W2b = Xb + 2u * TILE_H;

    const int tid  = threadIdx.x;
    const int wid  = tid >> 5;
    const int lane = tid & 31;
    const int w_m  = wid & 3;
    const int w_n  = wid >> 2;
    const int gq   = lane >> 2;
    const int tq   = lane & 3;
    const int lr   = lane & 7;
    const int g8   = lane >> 3;
    const int row0 = blockIdx.x * 128;

    const int arow = lr + ((g8 & 1) ? 8 : 0);
    const int acol = (g8 & 2) ? 8 : 0;
    const int brow = lr + ((g8 & 2) ? 8 : 0);
    const int bcol = (g8 & 1) ? 8 : 0;

    // ---- stage att + W1 + W2 (fp32 -> fp16) ----
    {
        const float4* Xg  = reinterpret_cast<const float4*>(att + (size_t)row0 * D_);
        const float4* Wg1 = reinterpret_cast<const float4*>(W1);
        const float4* Wg2 = reinterpret_cast<const float4*>(W2);
#pragma unroll
        for (int it = 0; it < 16; ++it) {
            int idx = tid + it * 256;
            int r = idx >> 5, c4 = idx & 31;
            uint32_t off = (uint32_t)(r * HS + c4 * 4) * 2u;
            float4 x4 = Xg[idx];
            sts64(Xb + off, f2h2(x4.x, x4.y), f2h2(x4.z, x4.w));
            float4 w1 = Wg1[idx];
            sts64(W1b + off, f2h2(w1.x, w1.y), f2h2(w1.z, w1.w));
            float4 w2 = Wg2[idx];
            sts64(W2b + off, f2h2(w2.x, w2.y), f2h2(w2.z, w2.w));
        }
    }
    __syncthreads();

    float acc[2][8][4];

    // ================= pass 1: h = relu(att @ W1^T + b1) =================
#pragma unroll
    for (int mi = 0; mi < 2; ++mi)
#pragma unroll
        for (int nt = 0; nt < 8; ++nt)
#pragma unroll
            for (int j = 0; j < 4; ++j) acc[mi][nt][j] = 0.f;

#pragma unroll
    for (int ks = 0; ks < 8; ++ks) {
        uint32_t xa[2][4];
#pragma unroll
        for (int mi = 0; mi < 2; ++mi)
            ldsm_x4(xa[mi][0], xa[mi][1], xa[mi][2], xa[mi][3],
                    Xb + (uint32_t)((w_m * 32 + mi * 16 + arow) * HS + ks * 16 + acol) * 2u);
#pragma unroll
        for (int np = 0; np < 4; ++np) {
            uint32_t r0, r1, r2, r3;
            ldsm_x4(r0, r1, r2, r3,
                    W1b + (uint32_t)((w_n * 64 + np * 16 + brow) * HS + ks * 16 + bcol) * 2u);
#pragma unroll
            for (int mi = 0; mi < 2; ++mi) {
                mma_f16(acc[mi][np * 2],     xa[mi][0], xa[mi][1], xa[mi][2], xa[mi][3], r0, r1);
                mma_f16(acc[mi][np * 2 + 1], xa[mi][0], xa[mi][1], xa[mi][2], xa[mi][3], r2, r3);
            }
        }
    }
    __syncthreads();   // all warps done reading Xb (att) before h overwrites it

    // h -> Xb (fp16), same layout
#pragma unroll
    for (int mi = 0; mi < 2; ++mi)
#pragma unroll
        for (int hi = 0; hi < 2; ++hi) {
            const int rl = w_m * 32 + mi * 16 + hi * 8 + gq;
#pragma unroll
            for (int nt = 0; nt < 8; ++nt) {
                int col = w_n * 64 + nt * 8 + 2 * tq;
                float2 bb = *reinterpret_cast<const float2*>(b1 + col);
                float v0 = fmaxf(acc[mi][nt][hi * 2]     + bb.x, 0.f);
                float v1 = fmaxf(acc[mi][nt][hi * 2 + 1] + bb.y, 0.f);
                sts32u(Xb + (uint32_t)(rl * HS + col) * 2u, f2h2(v0, v1));
            }
        }
    __syncthreads();

    // ================= pass 2: out = relu(h @ W2^T + b2) + att ============
#pragma unroll
    for (int mi = 0; mi < 2; ++mi)
#pragma unroll
        for (int nt = 0; nt < 8; ++nt)
#pragma unroll
            for (int j = 0; j < 4; ++j) acc[mi][nt][j] = 0.f;

#pragma unroll
    for (int ks = 0; ks < 8; ++ks) {
        uint32_t xa[2][4];
#pragma unroll
        for (int mi = 0; mi < 2; ++mi)
            ldsm_x4(xa[mi][0], xa[mi][1], xa[mi][2], xa[mi][3],
                    Xb + (uint32_t)((w_m * 32 + mi * 16 + arow) * HS + ks * 16 + acol) * 2u);
#pragma unroll
        for (int np = 0; np < 4; ++np) {
            uint32_t r0, r1, r2, r3;
            ldsm_x4(r0, r1, r2, r3,
                    W2b + (uint32_t)((w_n * 64 + np * 16 + brow) * HS + ks * 16 + bcol) * 2u);
#pragma unroll
            for (int mi = 0; mi < 2; ++mi) {
                mma_f16(acc[mi][np * 2],     xa[mi][0], xa[mi][1], xa[mi][2], xa[mi][3], r0, r1);
                mma_f16(acc[mi][np * 2 + 1], xa[mi][0], xa[mi][1], xa[mi][2], xa[mi][3], r2, r3);
            }
        }
    }

#pragma unroll
    for (int mi = 0; mi < 2; ++mi)
#pragma unroll
        for (int hi = 0; hi < 2; ++hi) {
            const int row = row0 + w_m * 32 + mi * 16 + hi * 8 + gq;
#pragma unroll
            for (int nt = 0; nt < 8; ++nt) {
                int col = w_n * 64 + nt * 8 + 2 * tq;
                float2 bb = *reinterpret_cast<const float2*>(b2 + col);
                size_t base = (size_t)row * D_ + col;
                float2 r2 = *reinterpret_cast<const float2*>(att + base);
                float v0 = fmaxf(acc[mi][nt][hi * 2]     + bb.x, 0.f) + r2.x;
                float v1 = fmaxf(acc[mi][nt][hi * 2 + 1] + bb.y, 0.f) + r2.y;
                *reinterpret_cast<float2*>(out + base) = make_float2(v0, v1);
            }
        }
}

// ---------------------------------------------------------------------------
extern "C" void kernel_launch(void* const* d_in, const int* in_sizes, int n_in,
                              void* d_out, int out_size)
{
    const float* x   = (const float*)d_in[0];
    const float* adj = (const float*)d_in[1];
    const float* Wq  = (const float*)d_in[2];
    const float* bq  = (const float*)d_in[3];
    const float* Wk  = (const float*)d_in[4];
    const float* bk  = (const float*)d_in[5];
    const float* Wv  = (const float*)d_in[6];
    const float* bv  = (const float*)d_in[7];
    const float* W1  = (const float*)d_in[8];
    const float* b1  = (const float*)d_in[9];
    const float* W2  = (const float*)d_in[10];
    const float* b2  = (const float*)d_in[11];
    float* out = (float*)d_out;

    __half *q, *k, *v;
    float *att;
    cudaGetSymbolAddress((void**)&q,   g_q);
    cudaGetSymbolAddress((void**)&k,   g_k);
    cudaGetSymbolAddress((void**)&v,   g_v);
    cudaGetSymbolAddress((void**)&att, g_att);

    const int M = B_ * N_;
    const size_t proj_smem = 2u * TILE_H;   // 69632 B
    const size_t ffn_smem  = 3u * TILE_H;   // 104448 B
    const size_t attn_smem = 5u * TILE_H;   // 174080 B
    cudaFuncSetAttribute(gemm_qkv3, cudaFuncAttributeMaxDynamicSharedMemorySize, (int)proj_smem);
    cudaFuncSetAttribute(gemm_ffn,  cudaFuncAttributeMaxDynamicSharedMemorySize, (int)ffn_smem);
    cudaFuncSetAttribute(attn_f16,  cudaFuncAttributeMaxDynamicSharedMemorySize, (int)attn_smem);

    dim3 pg(M / 128, 3);
    gemm_qkv3<<<pg, 256, proj_smem>>>(x, Wq, bq, Wk, bk, Wv, bv, q, k, v);

    dim3 ag(N_ / 128, B_);
    attn_f16<<<ag, 256, attn_smem>>>(q, k, v, adj, x, att);

    gemm_ffn<<<M / 128, 256, ffn_smem>>>(att, W1, b1, W2, b2, out);
}